// round 13
// baseline (speedup 1.0000x reference)
#include <cuda_runtime.h>
#include <cuda_bf16.h>
#include <cstdint>
#include <cstddef>

#define T_TOK   8192
#define HIDD    2048
#define NQKV    2560
#define DHEAD   256
#define NHEADS  8
#define SEQ     2048
#define NSLOTS  16384
#define KP2     4096        // 2-plane row: [hi 2048 | lo 2048]

// ---------------- scratch ----------------
__device__ float g_qkv[(size_t)T_TOK * NQKV];
__device__ __nv_bfloat16 g_packA[(size_t)T_TOK * KP2];
__device__ __nv_bfloat16 g_packB[(size_t)NQKV * KP2];
__device__ __nv_bfloat16 g_qpack[(size_t)T_TOK * NHEADS * 2 * DHEAD];
__device__ __nv_bfloat16 g_kpack[(size_t)T_TOK * 2 * DHEAD];
__device__ __nv_bfloat16 g_vpackT[(size_t)2 * DHEAD * T_TOK];

__device__ __forceinline__ uint32_t smem_u32(const void* p) {
    uint32_t a;
    asm("{ .reg .u64 t; cvta.to.shared.u64 t, %1; cvt.u32.u64 %0, t; }" : "=r"(a) : "l"(p));
    return a;
}

#define SWZ(o)   ((o) ^ (((o) >> 3) & 0x70))   // 128B rows
#define SWZ64(o) ((o) ^ (((o) >> 3) & 0x30))   // 64B rows

#define CP_ASYNC16(dst, src) \
    asm volatile("cp.async.cg.shared.global [%0], [%1], 16;" :: "r"(dst), "l"(src))
#define CP_COMMIT() asm volatile("cp.async.commit_group;" ::: "memory")
#define CP_WAIT(n)  asm volatile("cp.async.wait_group %0;" :: "n"(n) : "memory")

__device__ __forceinline__ void ldsm_x4(uint32_t* r, uint32_t addr) {
    asm volatile("ldmatrix.sync.aligned.m8n8.x4.shared.b16 {%0,%1,%2,%3}, [%4];"
        : "=r"(r[0]), "=r"(r[1]), "=r"(r[2]), "=r"(r[3]) : "r"(addr));
}

__device__ __forceinline__ void mma16816(float* d, const uint32_t* a, const uint32_t* b) {
    asm volatile(
        "mma.sync.aligned.m16n8k16.row.col.f32.bf16.bf16.f32 "
        "{%0,%1,%2,%3}, {%4,%5,%6,%7}, {%8,%9}, {%0,%1,%2,%3};"
        : "+f"(d[0]), "+f"(d[1]), "+f"(d[2]), "+f"(d[3])
        : "r"(a[0]), "r"(a[1]), "r"(a[2]), "r"(a[3]), "r"(b[0]), "r"(b[1]));
}

__device__ __forceinline__ uint32_t bf16pair(float a, float b) {
    __nv_bfloat16 ha = __float2bfloat16_rn(a), hb = __float2bfloat16_rn(b);
    uint16_t ua = *(uint16_t*)&ha, ub = *(uint16_t*)&hb;
    return (uint32_t)ua | ((uint32_t)ub << 16);
}

// ---------------------------------------------------------------------------
// Fused KV-cache passthrough copy.
// ---------------------------------------------------------------------------
__global__ void cachecopy_kernel(const float4* __restrict__ kc_in,
                                 const float4* __restrict__ vc_in,
                                 float4* __restrict__ kc_out,
                                 float4* __restrict__ vc_out)
{
    const long n = (long)NSLOTS * DHEAD / 4;
    long i = (long)blockIdx.x * blockDim.x + threadIdx.x;
    if (i < n) {
        kc_out[i] = kc_in[i];
        vc_out[i] = vc_in[i];
    }
}

// ---------------------------------------------------------------------------
// Pack fp32 -> 2-plane bf16 [hi | lo], vectorized.
// ---------------------------------------------------------------------------
__global__ void pack2_kernel(const float4* __restrict__ src,
                             __nv_bfloat16* __restrict__ dst, long total4)
{
    long idx = (long)blockIdx.x * blockDim.x + threadIdx.x;
    if (idx >= total4) return;
    float4 x = src[idx];
    long e = idx * 4;
    int k = (int)(e & 2047);
    long r = e >> 11;
    uint32_t hi0 = bf16pair(x.x, x.y);
    uint32_t hi1 = bf16pair(x.z, x.w);
    __nv_bfloat162 h0 = *(__nv_bfloat162*)&hi0;
    __nv_bfloat162 h1 = *(__nv_bfloat162*)&hi1;
    uint32_t lo0 = bf16pair(x.x - __bfloat162float(h0.x), x.y - __bfloat162float(h0.y));
    uint32_t lo1 = bf16pair(x.z - __bfloat162float(h1.x), x.w - __bfloat162float(h1.y));
    uint2* dhi = (uint2*)(dst + r * KP2 + k);
    uint2* dlo = (uint2*)(dst + r * KP2 + 2048 + k);
    *dhi = make_uint2(hi0, hi1);
    *dlo = make_uint2(lo0, lo1);
}

// ---------------------------------------------------------------------------
// 2-plane bf16x3 NT GEMM, occupancy-2 PERSISTENT version.
// BM=BN=128, BK=32 (SW64). 3 stages x 32KB = 96KB -> 2 CTAs/SM.
// Grid = 296; each CTA loops tiles with stride gridDim.x (no wave quantization).
// ---------------------------------------------------------------------------
#define PLANE3   8192
#define STAGE3   32768
#define NCH3     64

__global__ __launch_bounds__(256, 2)
void gemm_mma3_kernel(const __nv_bfloat16* __restrict__ A,
                      const __nv_bfloat16* __restrict__ B,
                      float* __restrict__ C, int ldc, int nTilesX, int nTiles)
{
    extern __shared__ char smc[];
    const uint32_t sbase = smem_u32(smc);
    const int tid  = threadIdx.x;
    const int warp = tid >> 5, lane = tid & 31;
    const int wm = (warp & 3) * 32;
    const int wn = (warp >> 2) * 64;

    const int lrow = tid >> 1;
    const int lu0  = (tid & 1) * 2;

    const uint32_t arow = wm + (lane & 15);
    const uint32_t acol16 = (lane >> 4) * 16;
    const uint32_t brow_lo = wn + (lane & 7) + ((lane >> 4) * 8);
    const uint32_t bcol16 = ((lane >> 3) & 1) * 16;

    for (int tile = blockIdx.x; tile < nTiles; tile += gridDim.x) {
        const int mBase = (tile / nTilesX) * 128;
        const int nBase = (tile % nTilesX) * 128;

        const char* Ag = (const char*)A + (size_t)(mBase + lrow) * (KP2 * 2) + lu0 * 16;
        const char* Bg = (const char*)B + (size_t)(nBase + lrow) * (KP2 * 2) + lu0 * 16;

#define LOAD_STAGE3(stage, chunk) do {                                        \
    uint32_t _s = sbase + (stage) * STAGE3;                                   \
    size_t _go = (size_t)(chunk) * 64;                                        \
    _Pragma("unroll")                                                         \
    for (int _u = 0; _u < 2; _u++) {                                          \
        uint32_t _sw = SWZ64((uint32_t)(lrow * 64 + (lu0 + _u) * 16));        \
        CP_ASYNC16(_s + _sw,              Ag + _go + _u * 16);                \
        CP_ASYNC16(_s + PLANE3 + _sw,     Ag + 4096 + _go + _u * 16);         \
        CP_ASYNC16(_s + 2 * PLANE3 + _sw, Bg + _go + _u * 16);                \
        CP_ASYNC16(_s + 3 * PLANE3 + _sw, Bg + 4096 + _go + _u * 16);         \
    } } while (0)

        float acc[2][8][4];
        #pragma unroll
        for (int i = 0; i < 2; i++)
            #pragma unroll
            for (int j = 0; j < 8; j++)
                #pragma unroll
                for (int q = 0; q < 4; q++) acc[i][j][q] = 0.f;

        LOAD_STAGE3(0, 0); CP_COMMIT();
        LOAD_STAGE3(1, 1); CP_COMMIT();

        int stage = 0;
        for (int it = 0; it < NCH3; it++) {
            CP_WAIT(1);
            __syncthreads();
            const uint32_t s0 = sbase + stage * STAGE3;

            #pragma unroll
            for (int ks = 0; ks < 2; ks++) {
                uint32_t aH0[4], aH1[4], aL0[4], aL1[4];
                uint32_t ao = arow * 64 + ks * 32 + acol16;
                uint32_t swa0 = SWZ64(ao), swa1 = SWZ64(ao + 16 * 64);
                ldsm_x4(aH0, s0 + swa0);
                ldsm_x4(aH1, s0 + swa1);
                ldsm_x4(aL0, s0 + PLANE3 + swa0);
                ldsm_x4(aL1, s0 + PLANE3 + swa1);
                #pragma unroll
                for (int nt = 0; nt < 4; nt++) {
                    uint32_t bo = (brow_lo + nt * 16) * 64 + ks * 32 + bcol16;
                    uint32_t swb = SWZ64(bo);
                    uint32_t bH[4], bL[4];
                    ldsm_x4(bH, s0 + 2 * PLANE3 + swb);
                    ldsm_x4(bL, s0 + 3 * PLANE3 + swb);
                    mma16816(acc[0][nt * 2],     aH0, &bH[0]);
                    mma16816(acc[0][nt * 2 + 1], aH0, &bH[2]);
                    mma16816(acc[1][nt * 2],     aH1, &bH[0]);
                    mma16816(acc[1][nt * 2 + 1], aH1, &bH[2]);
                    mma16816(acc[0][nt * 2],     aL0, &bH[0]);
                    mma16816(acc[0][nt * 2 + 1], aL0, &bH[2]);
                    mma16816(acc[1][nt * 2],     aL1, &bH[0]);
                    mma16816(acc[1][nt * 2 + 1], aL1, &bH[2]);
                    mma16816(acc[0][nt * 2],     aH0, &bL[0]);
                    mma16816(acc[0][nt * 2 + 1], aH0, &bL[2]);
                    mma16816(acc[1][nt * 2],     aH1, &bL[0]);
                    mma16816(acc[1][nt * 2 + 1], aH1, &bL[2]);
                }
            }

            int nx = it + 2;
            if (nx < NCH3) {
                int ns = stage + 2; if (ns >= 3) ns -= 3;
                LOAD_STAGE3(ns, nx);
            }
            CP_COMMIT();
            if (++stage == 3) stage = 0;
        }
#undef LOAD_STAGE3

        const int r0 = mBase + wm + (lane >> 2);
        const int c0 = nBase + wn + (lane & 3) * 2;
        #pragma unroll
        for (int mt = 0; mt < 2; mt++) {
            #pragma unroll
            for (int nt = 0; nt < 8; nt++) {
                const int r = r0 + mt * 16;
                const int c = c0 + nt * 8;
                *(float2*)&C[(size_t)r * ldc + c]       = make_float2(acc[mt][nt][0], acc[mt][nt][1]);
                *(float2*)&C[(size_t)(r + 8) * ldc + c] = make_float2(acc[mt][nt][2], acc[mt][nt][3]);
            }
        }
        __syncthreads();   // smem reuse guard before next tile's loads
    }
}

// ---------------------------------------------------------------------------
// Fused RoPE + Q/K pack + cache scatter + V transpose/split.
// ---------------------------------------------------------------------------
#define QSCL 0.09016844335f   // D^-1/2 * log2(e)

__global__ __launch_bounds__(512)
void ropevt_kernel(const float* __restrict__ qkv,
                   const float* __restrict__ cosp,
                   const float* __restrict__ sinp,
                   const int* __restrict__ slots,
                   float* __restrict__ kc_out,
                   float* __restrict__ vc_out,
                   __nv_bfloat16* __restrict__ qpack,
                   __nv_bfloat16* __restrict__ kpack,
                   __nv_bfloat16* __restrict__ vt)
{
    __shared__ float tile[64][33];
    const int tid = threadIdx.x;
    const int t0 = blockIdx.x * 64;

    #pragma unroll 4
    for (int i = 0; i < 16; i++) {
        int idx = i * 512 + tid;
        int d = idx & 127, tl = idx >> 7;
        int t = t0 + tl;
        const float c = cosp[t * 128 + d];
        const float s = sinp[t * 128 + d];
        const float* row = qkv + (size_t)t * NQKV;

        #pragma unroll
        for (int h = 0; h < NHEADS; h++) {
            float x1 = row[h * DHEAD + d], x2 = row[h * DHEAD + d + 128];
            float y1 = (x1 * c - x2 * s) * QSCL;
            float y2 = (x2 * c + x1 * s) * QSCL;
            __nv_bfloat16 h1 = __float2bfloat16_rn(y1);
            __nv_bfloat16 h2 = __float2bfloat16_rn(y2);
            __nv_bfloat16* qp = qpack + ((size_t)(t * NHEADS + h) * 2) * DHEAD;
            qp[d] = h1; qp[d + 128] = h2;
            qp[DHEAD + d]       = __float2bfloat16_rn(y1 - __bfloat162float(h1));
            qp[DHEAD + d + 128] = __float2bfloat16_rn(y2 - __bfloat162float(h2));
        }
        {
            float x1 = row[NHEADS * DHEAD + d], x2 = row[NHEADS * DHEAD + d + 128];
            float y1 = x1 * c - x2 * s;
            float y2 = x2 * c + x1 * s;
            const int slot = slots[t];
            kc_out[(size_t)slot * DHEAD + d]       = y1;
            kc_out[(size_t)slot * DHEAD + 128 + d] = y2;
            __nv_bfloat16 h1 = __float2bfloat16_rn(y1);
            __nv_bfloat16 h2 = __float2bfloat16_rn(y2);
            __nv_bfloat16* kp = kpack + (size_t)t * 2 * DHEAD;
            kp[d] = h1; kp[d + 128] = h2;
            kp[DHEAD + d]       = __float2bfloat16_rn(y1 - __bfloat162float(h1));
            kp[DHEAD + d + 128] = __float2bfloat16_rn(y2 - __bfloat162float(h2));
        }
        {
            const int slot = slots[t];
            float v1 = row[(NHEADS + 1) * DHEAD + d], v2 = row[(NHEADS + 1) * DHEAD + d + 128];
            vc_out[(size_t)slot * DHEAD + d]       = v1;
            vc_out[(size_t)slot * DHEAD + 128 + d] = v2;
        }
    }

    for (int d0 = 0; d0 < DHEAD; d0 += 32) {
        __syncthreads();
        #pragma unroll
        for (int w = 0; w < 4; w++) {
            int lin = w * 512 + tid;
            int dl = lin & 31, tl = lin >> 5;
            tile[tl][dl] = qkv[(size_t)(t0 + tl) * NQKV + (NHEADS + 1) * DHEAD + d0 + dl];
        }
        __syncthreads();
        #pragma unroll
        for (int w = 0; w < 4; w++) {
            int lin = w * 512 + tid;
            int dl = lin >> 6, tl = lin & 63;
            float x = tile[tl][dl];
            __nv_bfloat16 hi = __float2bfloat16_rn(x);
            __nv_bfloat16 lo = __float2bfloat16_rn(x - __bfloat162float(hi));
            size_t base = (size_t)(d0 + dl) * T_TOK + t0 + tl;
            vt[base] = hi;
            vt[(size_t)DHEAD * T_TOK + base] = lo;
        }
    }
}

// ---------------------------------------------------------------------------
// Tensor-core flash attention (bf16x3, Q hoisted), PERSISTENT version.
// Grid = 148; each CTA loops tiles (descending qb, stride-interleaved).
// ---------------------------------------------------------------------------
#define AQ_HI  0u
#define AQ_LO  32768u
#define AK_HI  65536u
#define AK_LO  98304u
#define AV_HI  131072u
#define AV_LO  163840u
#define AP_HI  196608u
#define AP_LO  204800u
#define ARED_M 212992u
#define ARED_S 213504u
#define AMS    214016u
#define ALS    214272u
#define ATTN_SMEM 214528
#define N_ATTN_TILES ((SEQ / 64) * NHEADS * 4)

__global__ __launch_bounds__(256, 1)
void attn_mma_kernel(const __nv_bfloat16* __restrict__ qpack,
                     const __nv_bfloat16* __restrict__ kpack,
                     const __nv_bfloat16* __restrict__ vpackT,
                     __nv_bfloat16* __restrict__ opack)
{
    extern __shared__ char smem[];
    const uint32_t sb = smem_u32(smem);
    float* smf = (float*)smem;

    const int tid  = threadIdx.x;
    const int warp = tid >> 5, lane = tid & 31;
    const int wm = warp & 3, wn = warp >> 2;

    const uint32_t arow   = (uint32_t)(wm * 16 + (lane & 15));
    const uint32_t acol16 = (uint32_t)((lane >> 4) * 16);
    const uint32_t brlo   = (uint32_t)((lane & 7) + ((lane >> 4) << 3));
    const uint32_t bcol16 = (uint32_t)(((lane >> 3) & 1) * 16);
    const int rbase = wm * 16 + (lane >> 2);

    for (int idx = blockIdx.x; idx < N_ATTN_TILES; idx += gridDim.x) {
        const int qb = (SEQ / 64 - 1) - (idx >> 5);   // descending qb blocks
        const int h  = (idx & 31) >> 2;
        const int b  = idx & 3;
        const int t0 = b * SEQ + qb * 64;

        // prologue: Q (both planes) + K tile 0
        {
            #pragma unroll
            for (int p = 0; p < 2; p++) {
                #pragma unroll
                for (int i = 0; i < 8; i++) {
                    int li = i * 256 + tid;
                    int tl = li >> 5, c16 = li & 31;
                    const char* src = (const char*)(qpack +
                        (((size_t)(t0 + tl) * NHEADS + h) * 2 + p) * DHEAD + c16 * 8);
                    uint32_t dst = sb + AQ_HI + p * 32768u +
                                   (uint32_t)(c16 >> 3) * 8192u +
                                   SWZ((uint32_t)(tl * 128 + (c16 & 7) * 16));
                    CP_ASYNC16(dst, src);
                }
            }
            int tk0 = b * SEQ;
            #pragma unroll
            for (int p = 0; p < 2; p++) {
                #pragma unroll
                for (int i = 0; i < 8; i++) {
                    int li = i * 256 + tid;
                    int tl = li >> 5, c16 = li & 31;
                    const char* src = (const char*)(kpack +
                        ((size_t)(tk0 + tl) * 2 + p) * DHEAD + c16 * 8);
                    uint32_t dst = sb + AK_HI + p * 32768u +
                                   (uint32_t)(c16 >> 3) * 8192u +
                                   SWZ((uint32_t)(tl * 128 + (c16 & 7) * 16));
                    CP_ASYNC16(dst, src);
                }
            }
            CP_COMMIT();
        }

        if (tid < 64) { smf[AMS / 4 + tid] = -1e30f; smf[ALS / 4 + tid] = 0.f; }

        float O[16][4];
        #pragma unroll
        for (int i = 0; i < 16; i++)
            #pragma unroll
            for (int j = 0; j < 4; j++) O[i][j] = 0.f;

        // hoist Q fragments into registers
        CP_WAIT(0);
        __syncthreads();
        uint32_t qf[2][16][4];
        #pragma unroll
        for (int p = 0; p < 2; p++)
            #pragma unroll
            for (int ks = 0; ks < 16; ks++) {
                uint32_t off = (uint32_t)(ks >> 2) * 8192u +
                               SWZ(arow * 128 + (ks & 3) * 32 + acol16);
                ldsm_x4(qf[p][ks], sb + (p ? AQ_LO : AQ_HI) + off);
            }

        for (int kt = 0; kt <= qb; kt++) {
            CP_WAIT(0);
            __syncthreads();

            const int tk0 = b * SEQ + kt * 64;
            // issue V(kt)
            #pragma unroll
            for (int p = 0; p < 2; p++) {
                #pragma unroll
                for (int i = 0; i < 8; i++) {
                    int li = i * 256 + tid;
                    int dl = li >> 3, c16 = li & 7;
                    const char* src = (const char*)(vpackT +
                        (size_t)p * DHEAD * T_TOK + (size_t)dl * T_TOK + tk0 + c16 * 8);
                    uint32_t dst = sb + AV_HI + p * 32768u +
                                   SWZ((uint32_t)(dl * 128 + c16 * 16));
                    CP_ASYNC16(dst, src);
                }
            }
            CP_COMMIT();

            // QK: S = Qhi.Khi + Qlo.Khi + Qhi.Klo
            float s[4][4];
            #pragma unroll
            for (int i = 0; i < 4; i++)
                #pragma unroll
                for (int j = 0; j < 4; j++) s[i][j] = 0.f;

            #pragma unroll
            for (int ks = 0; ks < 16; ks++) {
                const uint32_t blk = (uint32_t)(ks >> 2) * 8192u;
                #pragma unroll
                for (int nt = 0; nt < 2; nt++) {
                    uint32_t brow = (uint32_t)(wn * 32 + nt * 16) + brlo;
                    uint32_t swb = blk + SWZ(brow * 128 + (ks & 3) * 32 + bcol16);
                    uint32_t bH[4], bL[4];
                    ldsm_x4(bH, sb + AK_HI + swb);
                    ldsm_x4(bL, sb + AK_LO + swb);
                    mma16816(s[nt * 2],     qf[0][ks], &bH[0]);
                    mma16816(s[nt * 2 + 1], qf[0][ks], &bH[2]);
                    mma16816(s[nt * 2],     qf[1][ks], &bH[0]);
                    mma16816(s[nt * 2 + 1], qf[1][ks], &bH[2]);
                    mma16816(s[nt * 2],     qf[0][ks], &bL[0]);
                    mma16816(s[nt * 2 + 1], qf[0][ks], &bL[2]);
                }
            }

            if (kt == qb) {
                #pragma unroll
                for (int nf = 0; nf < 4; nf++) {
                    int c = wn * 32 + nf * 8 + (lane & 3) * 2;
                    #pragma unroll
                    for (int half = 0; half < 2; half++) {
                        int r = rbase + half * 8;
                        if (c     > r) s[nf][half * 2]     = -1e30f;
                        if (c + 1 > r) s[nf][half * 2 + 1] = -1e30f;
                    }
                }
            }

            #pragma unroll
            for (int half = 0; half < 2; half++) {
                float m = -1e30f;
                #pragma unroll
                for (int nf = 0; nf < 4; nf++)
                    m = fmaxf(m, fmaxf(s[nf][half * 2], s[nf][half * 2 + 1]));
                m = fmaxf(m, __shfl_xor_sync(0xffffffffu, m, 1));
                m = fmaxf(m, __shfl_xor_sync(0xffffffffu, m, 2));
                if ((lane & 3) == 0)
                    smf[ARED_M / 4 + wn * 64 + rbase + half * 8] = m;
            }
            __syncthreads();

            // issue K(kt+1)
            if (kt < qb) {
                const int tk1 = b * SEQ + (kt + 1) * 64;
                #pragma unroll
                for (int p = 0; p < 2; p++) {
                    #pragma unroll
                    for (int i = 0; i < 8; i++) {
                        int li = i * 256 + tid;
                        int tl = li >> 5, c16 = li & 31;
                        const char* src = (const char*)(kpack +
                            ((size_t)(tk1 + tl) * 2 + p) * DHEAD + c16 * 8);
                        uint32_t dst = sb + AK_HI + p * 32768u +
                                       (uint32_t)(c16 >> 3) * 8192u +
                                       SWZ((uint32_t)(tl * 128 + (c16 & 7) * 16));
                        CP_ASYNC16(dst, src);
                    }
                }
            }
            CP_COMMIT();

            float mnew[2], fh[2];
            #pragma unroll
            for (int half = 0; half < 2; half++) {
                int r = rbase + half * 8;
                float mprev = smf[AMS / 4 + r];
                float mn = fmaxf(mprev,
                           fmaxf(smf[ARED_M / 4 + r], smf[ARED_M / 4 + 64 + r]));
                mnew[half] = mn;
                fh[half] = exp2f(mprev - mn);
                float sum = 0.f;
                #pragma unroll
                for (int nf = 0; nf < 4; nf++) {
                    int c = wn * 32 + nf * 8 + (lane & 3) * 2;
                    float p0 = exp2f(s[nf][half * 2]     - mn);
                    float p1 = exp2f(s[nf][half * 2 + 1] - mn);
                    sum += p0 + p1;
                    __nv_bfloat16 h0 = __float2bfloat16_rn(p0);
                    __nv_bfloat16 h1 = __float2bfloat16_rn(p1);
                    float l0 = p0 - __bfloat162float(h0);
                    float l1 = p1 - __bfloat162float(h1);
                    uint32_t off = SWZ((uint32_t)(r * 128 + c * 2));
                    uint16_t u0 = *(uint16_t*)&h0, u1 = *(uint16_t*)&h1;
                    *(uint32_t*)(smem + AP_HI + off) = (uint32_t)u0 | ((uint32_t)u1 << 16);
                    *(uint32_t*)(smem + AP_LO + off) = bf16pair(l0, l1);
                }
                sum += __shfl_xor_sync(0xffffffffu, sum, 1);
                sum += __shfl_xor_sync(0xffffffffu, sum, 2);
                if ((lane & 3) == 0)
                    smf[ARED_S / 4 + wn * 64 + r] = sum;
            }
            #pragma unroll
            for (int nt = 0; nt < 16; nt++) {
                O[nt][0] *= fh[0]; O[nt][1] *= fh[0];
                O[nt][2] *= fh[1]; O[nt][3] *= fh[1];
            }

            CP_WAIT(1);
            __syncthreads();

            if (wn == 0 && (lane & 3) == 0) {
                #pragma unroll
                for (int half = 0; half < 2; half++) {
                    int r = rbase + half * 8;
                    smf[AMS / 4 + r] = mnew[half];
                    smf[ALS / 4 + r] = smf[ALS / 4 + r] * fh[half] +
                        smf[ARED_S / 4 + r] + smf[ARED_S / 4 + 64 + r];
                }
            }

            // PV: O += Phi.Vhi + Plo.Vhi + Phi.Vlo
            #pragma unroll
            for (int ks = 0; ks < 4; ks++) {
                uint32_t aH[4], aL[4];
                uint32_t ao = SWZ(arow * 128 + ks * 32 + acol16);
                ldsm_x4(aH, sb + AP_HI + ao);
                ldsm_x4(aL, sb + AP_LO + ao);
                #pragma unroll
                for (int nt = 0; nt < 8; nt++) {
                    uint32_t brow = (uint32_t)(wn * 128 + nt * 16) + brlo;
                    uint32_t bo = SWZ(brow * 128 + ks * 32 + bcol16);
                    uint32_t bH[4], bL[4];
                    ldsm_x4(bH, sb + AV_HI + bo);
                    ldsm_x4(bL, sb + AV_LO + bo);
                    mma16816(O[nt * 2],     aH, &bH[0]);
                    mma16816(O[nt * 2 + 1], aH, &bH[2]);
                    mma16816(O[nt * 2],     aL, &bH[0]);
                    mma16816(O[nt * 2 + 1], aL, &bH[2]);
                    mma16816(O[nt * 2],     aH, &bL[0]);
                    mma16816(O[nt * 2 + 1], aH, &bL[2]);
                }
            }
        }

        __syncthreads();

        // epilogue: normalize, write 2-plane o operand
        float inv0 = 1.0f / smf[ALS / 4 + rbase];
        float inv1 = 1.0f / smf[ALS / 4 + rbase + 8];
        #pragma unroll
        for (int half = 0; half < 2; half++) {
            const int r = rbase + half * 8;
            const float inv = half ? inv1 : inv0;
            __nv_bfloat16* orow = opack + (size_t)(t0 + r) * KP2 + h * DHEAD;
            #pragma unroll
            for (int nt = 0; nt < 16; nt++) {
                int c = wn * 128 + nt * 8 + (lane & 3) * 2;
                float o0 = O[nt][half * 2]     * inv;
                float o1 = O[nt][half * 2 + 1] * inv;
                __nv_bfloat16 h0 = __float2bfloat16_rn(o0);
                __nv_bfloat16 h1 = __float2bfloat16_rn(o1);
                uint32_t hi = (uint32_t)(*(uint16_t*)&h0) | ((uint32_t)(*(uint16_t*)&h1) << 16);
                uint32_t lo = bf16pair(o0 - __bfloat162float(h0), o1 - __bfloat162float(h1));
                *(uint32_t*)(orow + c)        = hi;
                *(uint32_t*)(orow + 2048 + c) = lo;
            }
        }
        __syncthreads();   // guard before next tile rewrites smem
    }
}

// ---------------------------------------------------------------------------
// Launch
// ---------------------------------------------------------------------------
extern "C" void kernel_launch(void* const* d_in, const int* in_sizes, int n_in,
                              void* d_out, int out_size)
{
    (void)in_sizes; (void)n_in; (void)out_size;
    const float* hidden = (const float*)d_in[0];
    const float* cosp   = (const float*)d_in[1];
    const float* sinp   = (const float*)d_in[2];
    const int*   slots  = (const int*)d_in[3];
    const float* kc_in  = (const float*)d_in[4];
    const float* vc_in  = (const float*)d_in[5];
    const float* wqkv   = (const float*)d_in[6];
    const float* wo     = (const float*)d_in[7];

    float* out    = (float*)d_out;
    float* kc_out = out + (size_t)T_TOK * HIDD;
    float* vc_out = kc_out + (size_t)NSLOTS * DHEAD;

    float* qkv = nullptr;
    __nv_bfloat16 *pA = nullptr, *pB = nullptr, *qp = nullptr, *kp = nullptr, *vt = nullptr;
    cudaGetSymbolAddress((void**)&qkv, g_qkv);
    cudaGetSymbolAddress((void**)&pA,  g_packA);
    cudaGetSymbolAddress((void**)&pB,  g_packB);
    cudaGetSymbolAddress((void**)&qp,  g_qpack);
    cudaGetSymbolAddress((void**)&kp,  g_kpack);
    cudaGetSymbolAddress((void**)&vt,  g_vpackT);

    const int gemm_smem = 3 * STAGE3;   // 98304 -> 2 CTAs/SM
    cudaFuncSetAttribute(gemm_mma3_kernel,
                         cudaFuncAttributeMaxDynamicSharedMemorySize, gemm_smem);
    cudaFuncSetAttribute(attn_mma_kernel,
                         cudaFuncAttributeMaxDynamicSharedMemorySize, ATTN_SMEM);

    // #1: fused cache passthrough
    {
        long n = (long)NSLOTS * DHEAD / 4;
        cachecopy_kernel<<<(unsigned)((n + 255) / 256), 256>>>(
            (const float4*)kc_in, (const float4*)vc_in,
            (float4*)kc_out, (float4*)vc_out);
    }

    // #2,#3: pack QKV-proj operands; #4: QKV projection (persistent, 296 CTAs)
    {
        long tA4 = (long)T_TOK * HIDD / 4;
        long tB4 = (long)NQKV * HIDD / 4;
        pack2_kernel<<<(unsigned)((tA4 + 255) / 256), 256>>>((const float4*)hidden, pA, tA4);
        pack2_kernel<<<(unsigned)((tB4 + 255) / 256), 256>>>((const float4*)wqkv,   pB, tB4);
        gemm_mma3_kernel<<<296, 256, gemm_smem>>>(pA, pB, qkv, NQKV,
                                                  NQKV / 128, (NQKV / 128) * (T_TOK / 128));
    }

    // #5: fused RoPE + packs + cache scatter + V transpose
    ropevt_kernel<<<T_TOK / 64, 512>>>(qkv, cosp, sinp, slots, kc_out, vc_out, qp, kp, vt);

    // #6: persistent tensor-core flash attention (148 CTAs)
    attn_mma_kernel<<<148, 256, ATTN_SMEM>>>(qp, kp, vt, pA);

    // #7: pack O-proj weights; #8: output projection (persistent)
    {
        long tB4 = (long)HIDD * HIDD / 4;
        pack2_kernel<<<(unsigned)((tB4 + 255) / 256), 256>>>((const float4*)wo, pB, tB4);
        gemm_mma3_kernel<<<296, 256, gemm_smem>>>(pA, pB, out, HIDD,
                                                  HIDD / 128, (HIDD / 128) * (T_TOK / 128));
    }
}

// round 14
// speedup vs baseline: 1.0191x; 1.0191x over previous
#include <cuda_runtime.h>
#include <cuda_bf16.h>
#include <cstdint>
#include <cstddef>

#define T_TOK   8192
#define HIDD    2048
#define NQKV    2560
#define DHEAD   256
#define NHEADS  8
#define SEQ     2048
#define NSLOTS  16384
#define KP2     4096        // 2-plane row: [hi 2048 | lo 2048]

// ---------------- scratch ----------------
__device__ float g_qkv[(size_t)T_TOK * NQKV];
__device__ __nv_bfloat16 g_packA[(size_t)T_TOK * KP2];
__device__ __nv_bfloat16 g_packB[(size_t)NQKV * KP2];
__device__ __nv_bfloat16 g_qpack[(size_t)T_TOK * NHEADS * 2 * DHEAD];
__device__ __nv_bfloat16 g_kpack[(size_t)T_TOK * 2 * DHEAD];
__device__ __nv_bfloat16 g_vpackT[(size_t)2 * DHEAD * T_TOK];

__device__ __forceinline__ uint32_t smem_u32(const void* p) {
    uint32_t a;
    asm("{ .reg .u64 t; cvta.to.shared.u64 t, %1; cvt.u32.u64 %0, t; }" : "=r"(a) : "l"(p));
    return a;
}

#define SWZ(o)   ((o) ^ (((o) >> 3) & 0x70))   // 128B rows
#define SWZ64(o) ((o) ^ (((o) >> 3) & 0x30))   // 64B rows

#define CP_ASYNC16(dst, src) \
    asm volatile("cp.async.cg.shared.global [%0], [%1], 16;" :: "r"(dst), "l"(src))
#define CP_COMMIT() asm volatile("cp.async.commit_group;" ::: "memory")
#define CP_WAIT(n)  asm volatile("cp.async.wait_group %0;" :: "n"(n) : "memory")

__device__ __forceinline__ void ldsm_x4(uint32_t* r, uint32_t addr) {
    asm volatile("ldmatrix.sync.aligned.m8n8.x4.shared.b16 {%0,%1,%2,%3}, [%4];"
        : "=r"(r[0]), "=r"(r[1]), "=r"(r[2]), "=r"(r[3]) : "r"(addr));
}

__device__ __forceinline__ void mma16816(float* d, const uint32_t* a, const uint32_t* b) {
    asm volatile(
        "mma.sync.aligned.m16n8k16.row.col.f32.bf16.bf16.f32 "
        "{%0,%1,%2,%3}, {%4,%5,%6,%7}, {%8,%9}, {%0,%1,%2,%3};"
        : "+f"(d[0]), "+f"(d[1]), "+f"(d[2]), "+f"(d[3])
        : "r"(a[0]), "r"(a[1]), "r"(a[2]), "r"(a[3]), "r"(b[0]), "r"(b[1]));
}

__device__ __forceinline__ uint32_t bf16pair(float a, float b) {
    __nv_bfloat16 ha = __float2bfloat16_rn(a), hb = __float2bfloat16_rn(b);
    uint16_t ua = *(uint16_t*)&ha, ub = *(uint16_t*)&hb;
    return (uint32_t)ua | ((uint32_t)ub << 16);
}

// ---------------------------------------------------------------------------
// Fused KV-cache passthrough copy.
// ---------------------------------------------------------------------------
__global__ void cachecopy_kernel(const float4* __restrict__ kc_in,
                                 const float4* __restrict__ vc_in,
                                 float4* __restrict__ kc_out,
                                 float4* __restrict__ vc_out)
{
    const long n = (long)NSLOTS * DHEAD / 4;
    long i = (long)blockIdx.x * blockDim.x + threadIdx.x;
    if (i < n) {
        kc_out[i] = kc_in[i];
        vc_out[i] = vc_in[i];
    }
}

// ---------------------------------------------------------------------------
// Pack fp32 -> 2-plane bf16 [hi | lo], vectorized.
// ---------------------------------------------------------------------------
__global__ void pack2_kernel(const float4* __restrict__ src,
                             __nv_bfloat16* __restrict__ dst, long total4)
{
    long idx = (long)blockIdx.x * blockDim.x + threadIdx.x;
    if (idx >= total4) return;
    float4 x = src[idx];
    long e = idx * 4;
    int k = (int)(e & 2047);
    long r = e >> 11;
    uint32_t hi0 = bf16pair(x.x, x.y);
    uint32_t hi1 = bf16pair(x.z, x.w);
    __nv_bfloat162 h0 = *(__nv_bfloat162*)&hi0;
    __nv_bfloat162 h1 = *(__nv_bfloat162*)&hi1;
    uint32_t lo0 = bf16pair(x.x - __bfloat162float(h0.x), x.y - __bfloat162float(h0.y));
    uint32_t lo1 = bf16pair(x.z - __bfloat162float(h1.x), x.w - __bfloat162float(h1.y));
    uint2* dhi = (uint2*)(dst + r * KP2 + k);
    uint2* dlo = (uint2*)(dst + r * KP2 + 2048 + k);
    *dhi = make_uint2(hi0, hi1);
    *dlo = make_uint2(lo0, lo1);
}

// ---------------------------------------------------------------------------
// 2-plane bf16x3 NT GEMM, occupancy-2, NON-persistent (R12 form — HW
// scheduler's dynamic backfill beats static stride for 4.3 tiles/CTA).
// BM=BN=128, BK=32 (SW64). 3 stages x 32KB = 96KB -> 2 CTAs/SM.
// ---------------------------------------------------------------------------
#define PLANE3   8192
#define STAGE3   32768
#define NCH3     64

__global__ __launch_bounds__(256, 2)
void gemm_mma3_kernel(const __nv_bfloat16* __restrict__ A,
                      const __nv_bfloat16* __restrict__ B,
                      float* __restrict__ C, int ldc)
{
    extern __shared__ char smc[];
    const uint32_t sbase = smem_u32(smc);
    const int tid  = threadIdx.x;
    const int warp = tid >> 5, lane = tid & 31;
    const int wm = (warp & 3) * 32;
    const int wn = (warp >> 2) * 64;
    const int mBase = blockIdx.y * 128;
    const int nBase = blockIdx.x * 128;

    const int lrow = tid >> 1;
    const int lu0  = (tid & 1) * 2;

    const char* Ag = (const char*)A + (size_t)(mBase + lrow) * (KP2 * 2) + lu0 * 16;
    const char* Bg = (const char*)B + (size_t)(nBase + lrow) * (KP2 * 2) + lu0 * 16;

#define LOAD_STAGE3(stage, chunk) do {                                        \
    uint32_t _s = sbase + (stage) * STAGE3;                                   \
    size_t _go = (size_t)(chunk) * 64;                                        \
    _Pragma("unroll")                                                         \
    for (int _u = 0; _u < 2; _u++) {                                          \
        uint32_t _sw = SWZ64((uint32_t)(lrow * 64 + (lu0 + _u) * 16));        \
        CP_ASYNC16(_s + _sw,              Ag + _go + _u * 16);                \
        CP_ASYNC16(_s + PLANE3 + _sw,     Ag + 4096 + _go + _u * 16);         \
        CP_ASYNC16(_s + 2 * PLANE3 + _sw, Bg + _go + _u * 16);                \
        CP_ASYNC16(_s + 3 * PLANE3 + _sw, Bg + 4096 + _go + _u * 16);         \
    } } while (0)

    float acc[2][8][4];
    #pragma unroll
    for (int i = 0; i < 2; i++)
        #pragma unroll
        for (int j = 0; j < 8; j++)
            #pragma unroll
            for (int q = 0; q < 4; q++) acc[i][j][q] = 0.f;

    LOAD_STAGE3(0, 0); CP_COMMIT();
    LOAD_STAGE3(1, 1); CP_COMMIT();

    const uint32_t arow = wm + (lane & 15);
    const uint32_t acol16 = (lane >> 4) * 16;
    const uint32_t brow_lo = wn + (lane & 7) + ((lane >> 4) * 8);
    const uint32_t bcol16 = ((lane >> 3) & 1) * 16;

    int stage = 0;
    for (int it = 0; it < NCH3; it++) {
        CP_WAIT(1);
        __syncthreads();
        const uint32_t s0 = sbase + stage * STAGE3;

        #pragma unroll
        for (int ks = 0; ks < 2; ks++) {
            uint32_t aH0[4], aH1[4], aL0[4], aL1[4];
            uint32_t ao = arow * 64 + ks * 32 + acol16;
            uint32_t swa0 = SWZ64(ao), swa1 = SWZ64(ao + 16 * 64);
            ldsm_x4(aH0, s0 + swa0);
            ldsm_x4(aH1, s0 + swa1);
            ldsm_x4(aL0, s0 + PLANE3 + swa0);
            ldsm_x4(aL1, s0 + PLANE3 + swa1);
            #pragma unroll
            for (int nt = 0; nt < 4; nt++) {
                uint32_t bo = (brow_lo + nt * 16) * 64 + ks * 32 + bcol16;
                uint32_t swb = SWZ64(bo);
                uint32_t bH[4], bL[4];
                ldsm_x4(bH, s0 + 2 * PLANE3 + swb);
                ldsm_x4(bL, s0 + 3 * PLANE3 + swb);
                mma16816(acc[0][nt * 2],     aH0, &bH[0]);
                mma16816(acc[0][nt * 2 + 1], aH0, &bH[2]);
                mma16816(acc[1][nt * 2],     aH1, &bH[0]);
                mma16816(acc[1][nt * 2 + 1], aH1, &bH[2]);
                mma16816(acc[0][nt * 2],     aL0, &bH[0]);
                mma16816(acc[0][nt * 2 + 1], aL0, &bH[2]);
                mma16816(acc[1][nt * 2],     aL1, &bH[0]);
                mma16816(acc[1][nt * 2 + 1], aL1, &bH[2]);
                mma16816(acc[0][nt * 2],     aH0, &bL[0]);
                mma16816(acc[0][nt * 2 + 1], aH0, &bL[2]);
                mma16816(acc[1][nt * 2],     aH1, &bL[0]);
                mma16816(acc[1][nt * 2 + 1], aH1, &bL[2]);
            }
        }

        int nx = it + 2;
        if (nx < NCH3) {
            int ns = stage + 2; if (ns >= 3) ns -= 3;
            LOAD_STAGE3(ns, nx);
        }
        CP_COMMIT();
        if (++stage == 3) stage = 0;
    }
#undef LOAD_STAGE3

    const int r0 = mBase + wm + (lane >> 2);
    const int c0 = nBase + wn + (lane & 3) * 2;
    #pragma unroll
    for (int mt = 0; mt < 2; mt++) {
        #pragma unroll
        for (int nt = 0; nt < 8; nt++) {
            const int r = r0 + mt * 16;
            const int c = c0 + nt * 8;
            *(float2*)&C[(size_t)r * ldc + c]       = make_float2(acc[mt][nt][0], acc[mt][nt][1]);
            *(float2*)&C[(size_t)(r + 8) * ldc + c] = make_float2(acc[mt][nt][2], acc[mt][nt][3]);
        }
    }
}

// ---------------------------------------------------------------------------
// Fused RoPE + Q/K pack + cache scatter + V transpose/split.
// ---------------------------------------------------------------------------
#define QSCL 0.09016844335f   // D^-1/2 * log2(e)

__global__ __launch_bounds__(512)
void ropevt_kernel(const float* __restrict__ qkv,
                   const float* __restrict__ cosp,
                   const float* __restrict__ sinp,
                   const int* __restrict__ slots,
                   float* __restrict__ kc_out,
                   float* __restrict__ vc_out,
                   __nv_bfloat16* __restrict__ qpack,
                   __nv_bfloat16* __restrict__ kpack,
                   __nv_bfloat16* __restrict__ vt)
{
    __shared__ float tile[64][33];
    const int tid = threadIdx.x;
    const int t0 = blockIdx.x * 64;

    #pragma unroll 4
    for (int i = 0; i < 16; i++) {
        int idx = i * 512 + tid;
        int d = idx & 127, tl = idx >> 7;
        int t = t0 + tl;
        const float c = cosp[t * 128 + d];
        const float s = sinp[t * 128 + d];
        const float* row = qkv + (size_t)t * NQKV;

        #pragma unroll
        for (int h = 0; h < NHEADS; h++) {
            float x1 = row[h * DHEAD + d], x2 = row[h * DHEAD + d + 128];
            float y1 = (x1 * c - x2 * s) * QSCL;
            float y2 = (x2 * c + x1 * s) * QSCL;
            __nv_bfloat16 h1 = __float2bfloat16_rn(y1);
            __nv_bfloat16 h2 = __float2bfloat16_rn(y2);
            __nv_bfloat16* qp = qpack + ((size_t)(t * NHEADS + h) * 2) * DHEAD;
            qp[d] = h1; qp[d + 128] = h2;
            qp[DHEAD + d]       = __float2bfloat16_rn(y1 - __bfloat162float(h1));
            qp[DHEAD + d + 128] = __float2bfloat16_rn(y2 - __bfloat162float(h2));
        }
        {
            float x1 = row[NHEADS * DHEAD + d], x2 = row[NHEADS * DHEAD + d + 128];
            float y1 = x1 * c - x2 * s;
            float y2 = x2 * c + x1 * s;
            const int slot = slots[t];
            kc_out[(size_t)slot * DHEAD + d]       = y1;
            kc_out[(size_t)slot * DHEAD + 128 + d] = y2;
            __nv_bfloat16 h1 = __float2bfloat16_rn(y1);
            __nv_bfloat16 h2 = __float2bfloat16_rn(y2);
            __nv_bfloat16* kp = kpack + (size_t)t * 2 * DHEAD;
            kp[d] = h1; kp[d + 128] = h2;
            kp[DHEAD + d]       = __float2bfloat16_rn(y1 - __bfloat162float(h1));
            kp[DHEAD + d + 128] = __float2bfloat16_rn(y2 - __bfloat162float(h2));
        }
        {
            const int slot = slots[t];
            float v1 = row[(NHEADS + 1) * DHEAD + d], v2 = row[(NHEADS + 1) * DHEAD + d + 128];
            vc_out[(size_t)slot * DHEAD + d]       = v1;
            vc_out[(size_t)slot * DHEAD + 128 + d] = v2;
        }
    }

    for (int d0 = 0; d0 < DHEAD; d0 += 32) {
        __syncthreads();
        #pragma unroll
        for (int w = 0; w < 4; w++) {
            int lin = w * 512 + tid;
            int dl = lin & 31, tl = lin >> 5;
            tile[tl][dl] = qkv[(size_t)(t0 + tl) * NQKV + (NHEADS + 1) * DHEAD + d0 + dl];
        }
        __syncthreads();
        #pragma unroll
        for (int w = 0; w < 4; w++) {
            int lin = w * 512 + tid;
            int dl = lin >> 6, tl = lin & 63;
            float x = tile[tl][dl];
            __nv_bfloat16 hi = __float2bfloat16_rn(x);
            __nv_bfloat16 lo = __float2bfloat16_rn(x - __bfloat162float(hi));
            size_t base = (size_t)(d0 + dl) * T_TOK + t0 + tl;
            vt[base] = hi;
            vt[(size_t)DHEAD * T_TOK + base] = lo;
        }
    }
}

// ---------------------------------------------------------------------------
// Tensor-core flash attention (bf16x3, Q hoisted), PERSISTENT (kept from R13
// — measured ~570us vs ~690 non-persistent).
// ---------------------------------------------------------------------------
#define AQ_HI  0u
#define AQ_LO  32768u
#define AK_HI  65536u
#define AK_LO  98304u
#define AV_HI  131072u
#define AV_LO  163840u
#define AP_HI  196608u
#define AP_LO  204800u
#define ARED_M 212992u
#define ARED_S 213504u
#define AMS    214016u
#define ALS    214272u
#define ATTN_SMEM 214528
#define N_ATTN_TILES ((SEQ / 64) * NHEADS * 4)

__global__ __launch_bounds__(256, 1)
void attn_mma_kernel(const __nv_bfloat16* __restrict__ qpack,
                     const __nv_bfloat16* __restrict__ kpack,
                     const __nv_bfloat16* __restrict__ vpackT,
                     __nv_bfloat16* __restrict__ opack)
{
    extern __shared__ char smem[];
    const uint32_t sb = smem_u32(smem);
    float* smf = (float*)smem;

    const int tid  = threadIdx.x;
    const int warp = tid >> 5, lane = tid & 31;
    const int wm = warp & 3, wn = warp >> 2;

    const uint32_t arow   = (uint32_t)(wm * 16 + (lane & 15));
    const uint32_t acol16 = (uint32_t)((lane >> 4) * 16);
    const uint32_t brlo   = (uint32_t)((lane & 7) + ((lane >> 4) << 3));
    const uint32_t bcol16 = (uint32_t)(((lane >> 3) & 1) * 16);
    const int rbase = wm * 16 + (lane >> 2);

    for (int idx = blockIdx.x; idx < N_ATTN_TILES; idx += gridDim.x) {
        const int qb = (SEQ / 64 - 1) - (idx >> 5);   // descending qb blocks
        const int h  = (idx & 31) >> 2;
        const int b  = idx & 3;
        const int t0 = b * SEQ + qb * 64;

        // prologue: Q (both planes) + K tile 0
        {
            #pragma unroll
            for (int p = 0; p < 2; p++) {
                #pragma unroll
                for (int i = 0; i < 8; i++) {
                    int li = i * 256 + tid;
                    int tl = li >> 5, c16 = li & 31;
                    const char* src = (const char*)(qpack +
                        (((size_t)(t0 + tl) * NHEADS + h) * 2 + p) * DHEAD + c16 * 8);
                    uint32_t dst = sb + AQ_HI + p * 32768u +
                                   (uint32_t)(c16 >> 3) * 8192u +
                                   SWZ((uint32_t)(tl * 128 + (c16 & 7) * 16));
                    CP_ASYNC16(dst, src);
                }
            }
            int tk0 = b * SEQ;
            #pragma unroll
            for (int p = 0; p < 2; p++) {
                #pragma unroll
                for (int i = 0; i < 8; i++) {
                    int li = i * 256 + tid;
                    int tl = li >> 5, c16 = li & 31;
                    const char* src = (const char*)(kpack +
                        ((size_t)(tk0 + tl) * 2 + p) * DHEAD + c16 * 8);
                    uint32_t dst = sb + AK_HI + p * 32768u +
                                   (uint32_t)(c16 >> 3) * 8192u +
                                   SWZ((uint32_t)(tl * 128 + (c16 & 7) * 16));
                    CP_ASYNC16(dst, src);
                }
            }
            CP_COMMIT();
        }

        if (tid < 64) { smf[AMS / 4 + tid] = -1e30f; smf[ALS / 4 + tid] = 0.f; }

        float O[16][4];
        #pragma unroll
        for (int i = 0; i < 16; i++)
            #pragma unroll
            for (int j = 0; j < 4; j++) O[i][j] = 0.f;

        // hoist Q fragments into registers
        CP_WAIT(0);
        __syncthreads();
        uint32_t qf[2][16][4];
        #pragma unroll
        for (int p = 0; p < 2; p++)
            #pragma unroll
            for (int ks = 0; ks < 16; ks++) {
                uint32_t off = (uint32_t)(ks >> 2) * 8192u +
                               SWZ(arow * 128 + (ks & 3) * 32 + acol16);
                ldsm_x4(qf[p][ks], sb + (p ? AQ_LO : AQ_HI) + off);
            }

        for (int kt = 0; kt <= qb; kt++) {
            CP_WAIT(0);
            __syncthreads();

            const int tk0 = b * SEQ + kt * 64;
            // issue V(kt)
            #pragma unroll
            for (int p = 0; p < 2; p++) {
                #pragma unroll
                for (int i = 0; i < 8; i++) {
                    int li = i * 256 + tid;
                    int dl = li >> 3, c16 = li & 7;
                    const char* src = (const char*)(vpackT +
                        (size_t)p * DHEAD * T_TOK + (size_t)dl * T_TOK + tk0 + c16 * 8);
                    uint32_t dst = sb + AV_HI + p * 32768u +
                                   SWZ((uint32_t)(dl * 128 + c16 * 16));
                    CP_ASYNC16(dst, src);
                }
            }
            CP_COMMIT();

            // QK: S = Qhi.Khi + Qlo.Khi + Qhi.Klo
            float s[4][4];
            #pragma unroll
            for (int i = 0; i < 4; i++)
                #pragma unroll
                for (int j = 0; j < 4; j++) s[i][j] = 0.f;

            #pragma unroll
            for (int ks = 0; ks < 16; ks++) {
                const uint32_t blk = (uint32_t)(ks >> 2) * 8192u;
                #pragma unroll
                for (int nt = 0; nt < 2; nt++) {
                    uint32_t brow = (uint32_t)(wn * 32 + nt * 16) + brlo;
                    uint32_t swb = blk + SWZ(brow * 128 + (ks & 3) * 32 + bcol16);
                    uint32_t bH[4], bL[4];
                    ldsm_x4(bH, sb + AK_HI + swb);
                    ldsm_x4(bL, sb + AK_LO + swb);
                    mma16816(s[nt * 2],     qf[0][ks], &bH[0]);
                    mma16816(s[nt * 2 + 1], qf[0][ks], &bH[2]);
                    mma16816(s[nt * 2],     qf[1][ks], &bH[0]);
                    mma16816(s[nt * 2 + 1], qf[1][ks], &bH[2]);
                    mma16816(s[nt * 2],     qf[0][ks], &bL[0]);
                    mma16816(s[nt * 2 + 1], qf[0][ks], &bL[2]);
                }
            }

            if (kt == qb) {
                #pragma unroll
                for (int nf = 0; nf < 4; nf++) {
                    int c = wn * 32 + nf * 8 + (lane & 3) * 2;
                    #pragma unroll
                    for (int half = 0; half < 2; half++) {
                        int r = rbase + half * 8;
                        if (c     > r) s[nf][half * 2]     = -1e30f;
                        if (c + 1 > r) s[nf][half * 2 + 1] = -1e30f;
                    }
                }
            }

            #pragma unroll
            for (int half = 0; half < 2; half++) {
                float m = -1e30f;
                #pragma unroll
                for (int nf = 0; nf < 4; nf++)
                    m = fmaxf(m, fmaxf(s[nf][half * 2], s[nf][half * 2 + 1]));
                m = fmaxf(m, __shfl_xor_sync(0xffffffffu, m, 1));
                m = fmaxf(m, __shfl_xor_sync(0xffffffffu, m, 2));
                if ((lane & 3) == 0)
                    smf[ARED_M / 4 + wn * 64 + rbase + half * 8] = m;
            }
            __syncthreads();

            // issue K(kt+1)
            if (kt < qb) {
                const int tk1 = b * SEQ + (kt + 1) * 64;
                #pragma unroll
                for (int p = 0; p < 2; p++) {
                    #pragma unroll
                    for (int i = 0; i < 8; i++) {
                        int li = i * 256 + tid;
                        int tl = li >> 5, c16 = li & 31;
                        const char* src = (const char*)(kpack +
                            ((size_t)(tk1 + tl) * 2 + p) * DHEAD + c16 * 8);
                        uint32_t dst = sb + AK_HI + p * 32768u +
                                       (uint32_t)(c16 >> 3) * 8192u +
                                       SWZ((uint32_t)(tl * 128 + (c16 & 7) * 16));
                        CP_ASYNC16(dst, src);
                    }
                }
            }
            CP_COMMIT();

            float mnew[2], fh[2];
            #pragma unroll
            for (int half = 0; half < 2; half++) {
                int r = rbase + half * 8;
                float mprev = smf[AMS / 4 + r];
                float mn = fmaxf(mprev,
                           fmaxf(smf[ARED_M / 4 + r], smf[ARED_M / 4 + 64 + r]));
                mnew[half] = mn;
                fh[half] = exp2f(mprev - mn);
                float sum = 0.f;
                #pragma unroll
                for (int nf = 0; nf < 4; nf++) {
                    int c = wn * 32 + nf * 8 + (lane & 3) * 2;
                    float p0 = exp2f(s[nf][half * 2]     - mn);
                    float p1 = exp2f(s[nf][half * 2 + 1] - mn);
                    sum += p0 + p1;
                    __nv_bfloat16 h0 = __float2bfloat16_rn(p0);
                    __nv_bfloat16 h1 = __float2bfloat16_rn(p1);
                    float l0 = p0 - __bfloat162float(h0);
                    float l1 = p1 - __bfloat162float(h1);
                    uint32_t off = SWZ((uint32_t)(r * 128 + c * 2));
                    uint16_t u0 = *(uint16_t*)&h0, u1 = *(uint16_t*)&h1;
                    *(uint32_t*)(smem + AP_HI + off) = (uint32_t)u0 | ((uint32_t)u1 << 16);
                    *(uint32_t*)(smem + AP_LO + off) = bf16pair(l0, l1);
                }
                sum += __shfl_xor_sync(0xffffffffu, sum, 1);
                sum += __shfl_xor_sync(0xffffffffu, sum, 2);
                if ((lane & 3) == 0)
                    smf[ARED_S / 4 + wn * 64 + r] = sum;
            }
            #pragma unroll
            for (int nt = 0; nt < 16; nt++) {
                O[nt][0] *= fh[0]; O[nt][1] *= fh[0];
                O[nt][2] *= fh[1]; O[nt][3] *= fh[1];
            }

            CP_WAIT(1);
            __syncthreads();

            if (wn == 0 && (lane & 3) == 0) {
                #pragma unroll
                for (int half = 0; half < 2; half++) {
                    int r = rbase + half * 8;
                    smf[AMS / 4 + r] = mnew[half];
                    smf[ALS / 4 + r] = smf[ALS / 4 + r] * fh[half] +
                        smf[ARED_S / 4 + r] + smf[ARED_S / 4 + 64 + r];
                }
            }

            // PV: O += Phi.Vhi + Plo.Vhi + Phi.Vlo
            #pragma unroll
            for (int ks = 0; ks < 4; ks++) {
                uint32_t aH[4], aL[4];
                uint32_t ao = SWZ(arow * 128 + ks * 32 + acol16);
                ldsm_x4(aH, sb + AP_HI + ao);
                ldsm_x4(aL, sb + AP_LO + ao);
                #pragma unroll
                for (int nt = 0; nt < 8; nt++) {
                    uint32_t brow = (uint32_t)(wn * 128 + nt * 16) + brlo;
                    uint32_t bo = SWZ(brow * 128 + ks * 32 + bcol16);
                    uint32_t bH[4], bL[4];
                    ldsm_x4(bH, sb + AV_HI + bo);
                    ldsm_x4(bL, sb + AV_LO + bo);
                    mma16816(O[nt * 2],     aH, &bH[0]);
                    mma16816(O[nt * 2 + 1], aH, &bH[2]);
                    mma16816(O[nt * 2],     aL, &bH[0]);
                    mma16816(O[nt * 2 + 1], aL, &bH[2]);
                    mma16816(O[nt * 2],     aH, &bL[0]);
                    mma16816(O[nt * 2 + 1], aH, &bL[2]);
                }
            }
        }

        __syncthreads();

        // epilogue: normalize, write 2-plane o operand
        float inv0 = 1.0f / smf[ALS / 4 + rbase];
        float inv1 = 1.0f / smf[ALS / 4 + rbase + 8];
        #pragma unroll
        for (int half = 0; half < 2; half++) {
            const int r = rbase + half * 8;
            const float inv = half ? inv1 : inv0;
            __nv_bfloat16* orow = opack + (size_t)(t0 + r) * KP2 + h * DHEAD;
            #pragma unroll
            for (int nt = 0; nt < 16; nt++) {
                int c = wn * 128 + nt * 8 + (lane & 3) * 2;
                float o0 = O[nt][half * 2]     * inv;
                float o1 = O[nt][half * 2 + 1] * inv;
                __nv_bfloat16 h0 = __float2bfloat16_rn(o0);
                __nv_bfloat16 h1 = __float2bfloat16_rn(o1);
                uint32_t hi = (uint32_t)(*(uint16_t*)&h0) | ((uint32_t)(*(uint16_t*)&h1) << 16);
                uint32_t lo = bf16pair(o0 - __bfloat162float(h0), o1 - __bfloat162float(h1));
                *(uint32_t*)(orow + c)        = hi;
                *(uint32_t*)(orow + 2048 + c) = lo;
            }
        }
        __syncthreads();   // guard before next tile rewrites smem
    }
}

// ---------------------------------------------------------------------------
// Launch
// ---------------------------------------------------------------------------
extern "C" void kernel_launch(void* const* d_in, const int* in_sizes, int n_in,
                              void* d_out, int out_size)
{
    (void)in_sizes; (void)n_in; (void)out_size;
    const float* hidden = (const float*)d_in[0];
    const float* cosp   = (const float*)d_in[1];
    const float* sinp   = (const float*)d_in[2];
    const int*   slots  = (const int*)d_in[3];
    const float* kc_in  = (const float*)d_in[4];
    const float* vc_in  = (const float*)d_in[5];
    const float* wqkv   = (const float*)d_in[6];
    const float* wo     = (const float*)d_in[7];

    float* out    = (float*)d_out;
    float* kc_out = out + (size_t)T_TOK * HIDD;
    float* vc_out = kc_out + (size_t)NSLOTS * DHEAD;

    float* qkv = nullptr;
    __nv_bfloat16 *pA = nullptr, *pB = nullptr, *qp = nullptr, *kp = nullptr, *vt = nullptr;
    cudaGetSymbolAddress((void**)&qkv, g_qkv);
    cudaGetSymbolAddress((void**)&pA,  g_packA);
    cudaGetSymbolAddress((void**)&pB,  g_packB);
    cudaGetSymbolAddress((void**)&qp,  g_qpack);
    cudaGetSymbolAddress((void**)&kp,  g_kpack);
    cudaGetSymbolAddress((void**)&vt,  g_vpackT);

    const int gemm_smem = 3 * STAGE3;   // 98304 -> 2 CTAs/SM
    cudaFuncSetAttribute(gemm_mma3_kernel,
                         cudaFuncAttributeMaxDynamicSharedMemorySize, gemm_smem);
    cudaFuncSetAttribute(attn_mma_kernel,
                         cudaFuncAttributeMaxDynamicSharedMemorySize, ATTN_SMEM);

    // #1: fused cache passthrough
    {
        long n = (long)NSLOTS * DHEAD / 4;
        cachecopy_kernel<<<(unsigned)((n + 255) / 256), 256>>>(
            (const float4*)kc_in, (const float4*)vc_in,
            (float4*)kc_out, (float4*)vc_out);
    }

    // #2,#3: pack QKV-proj operands; #4: QKV projection (non-persistent)
    {
        long tA4 = (long)T_TOK * HIDD / 4;
        long tB4 = (long)NQKV * HIDD / 4;
        pack2_kernel<<<(unsigned)((tA4 + 255) / 256), 256>>>((const float4*)hidden, pA, tA4);
        pack2_kernel<<<(unsigned)((tB4 + 255) / 256), 256>>>((const float4*)wqkv,   pB, tB4);
        gemm_mma3_kernel<<<dim3(NQKV / 128, T_TOK / 128), 256, gemm_smem>>>(pA, pB, qkv, NQKV);
    }

    // #5: fused RoPE + packs + cache scatter + V transpose
    ropevt_kernel<<<T_TOK / 64, 512>>>(qkv, cosp, sinp, slots, kc_out, vc_out, qp, kp, vt);

    // #6: persistent tensor-core flash attention (148 CTAs)
    attn_mma_kernel<<<148, 256, ATTN_SMEM>>>(qp, kp, vt, pA);

    // #7: pack O-proj weights; #8: output projection (non-persistent)
    {
        long tB4 = (long)HIDD * HIDD / 4;
        pack2_kernel<<<(unsigned)((tB4 + 255) / 256), 256>>>((const float4*)wo, pB, tB4);
        gemm_mma3_kernel<<<dim3(HIDD / 128, T_TOK / 128), 256, gemm_smem>>>(pA, pB, out, HIDD);
    }
}

// round 15
// speedup vs baseline: 1.0828x; 1.0625x over previous
#include <cuda_runtime.h>
#include <cuda_bf16.h>
#include <cstdint>
#include <cstddef>

#define T_TOK   8192
#define HIDD    2048
#define NQKV    2560
#define DHEAD   256
#define NHEADS  8
#define SEQ     2048
#define NSLOTS  16384
#define KP2     4096        // 2-plane row: [hi 2048 | lo 2048]

// ---------------- scratch ----------------
__device__ float g_qkv[(size_t)T_TOK * NQKV];
__device__ __nv_bfloat16 g_packA[(size_t)T_TOK * KP2];
__device__ __nv_bfloat16 g_packB[(size_t)NQKV * KP2];
__device__ __nv_bfloat16 g_qpack[(size_t)T_TOK * NHEADS * 2 * DHEAD];
__device__ __nv_bfloat16 g_kpack[(size_t)T_TOK * 2 * DHEAD];
__device__ __nv_bfloat16 g_vpackT[(size_t)2 * DHEAD * T_TOK];

__device__ __forceinline__ uint32_t smem_u32(const void* p) {
    uint32_t a;
    asm("{ .reg .u64 t; cvta.to.shared.u64 t, %1; cvt.u32.u64 %0, t; }" : "=r"(a) : "l"(p));
    return a;
}

#define SWZ(o)   ((o) ^ (((o) >> 3) & 0x70))   // 128B rows
#define SWZ64(o) ((o) ^ (((o) >> 3) & 0x30))   // 64B rows

#define CP_ASYNC16(dst, src) \
    asm volatile("cp.async.cg.shared.global [%0], [%1], 16;" :: "r"(dst), "l"(src))
#define CP_COMMIT() asm volatile("cp.async.commit_group;" ::: "memory")
#define CP_WAIT(n)  asm volatile("cp.async.wait_group %0;" :: "n"(n) : "memory")

__device__ __forceinline__ void ldsm_x4(uint32_t* r, uint32_t addr) {
    asm volatile("ldmatrix.sync.aligned.m8n8.x4.shared.b16 {%0,%1,%2,%3}, [%4];"
        : "=r"(r[0]), "=r"(r[1]), "=r"(r[2]), "=r"(r[3]) : "r"(addr));
}

__device__ __forceinline__ void mma16816(float* d, const uint32_t* a, const uint32_t* b) {
    asm volatile(
        "mma.sync.aligned.m16n8k16.row.col.f32.bf16.bf16.f32 "
        "{%0,%1,%2,%3}, {%4,%5,%6,%7}, {%8,%9}, {%0,%1,%2,%3};"
        : "+f"(d[0]), "+f"(d[1]), "+f"(d[2]), "+f"(d[3])
        : "r"(a[0]), "r"(a[1]), "r"(a[2]), "r"(a[3]), "r"(b[0]), "r"(b[1]));
}

__device__ __forceinline__ uint32_t bf16pair(float a, float b) {
    __nv_bfloat16 ha = __float2bfloat16_rn(a), hb = __float2bfloat16_rn(b);
    uint16_t ua = *(uint16_t*)&ha, ub = *(uint16_t*)&hb;
    return (uint32_t)ua | ((uint32_t)ub << 16);
}

// ---------------------------------------------------------------------------
// Fused KV-cache passthrough copy.
// ---------------------------------------------------------------------------
__global__ void cachecopy_kernel(const float4* __restrict__ kc_in,
                                 const float4* __restrict__ vc_in,
                                 float4* __restrict__ kc_out,
                                 float4* __restrict__ vc_out)
{
    const long n = (long)NSLOTS * DHEAD / 4;
    long i = (long)blockIdx.x * blockDim.x + threadIdx.x;
    if (i < n) {
        kc_out[i] = kc_in[i];
        vc_out[i] = vc_in[i];
    }
}

// ---------------------------------------------------------------------------
// Pack fp32 -> 2-plane bf16 [hi | lo], vectorized.
// ---------------------------------------------------------------------------
__global__ void pack2_kernel(const float4* __restrict__ src,
                             __nv_bfloat16* __restrict__ dst, long total4)
{
    long idx = (long)blockIdx.x * blockDim.x + threadIdx.x;
    if (idx >= total4) return;
    float4 x = src[idx];
    long e = idx * 4;
    int k = (int)(e & 2047);
    long r = e >> 11;
    uint32_t hi0 = bf16pair(x.x, x.y);
    uint32_t hi1 = bf16pair(x.z, x.w);
    __nv_bfloat162 h0 = *(__nv_bfloat162*)&hi0;
    __nv_bfloat162 h1 = *(__nv_bfloat162*)&hi1;
    uint32_t lo0 = bf16pair(x.x - __bfloat162float(h0.x), x.y - __bfloat162float(h0.y));
    uint32_t lo1 = bf16pair(x.z - __bfloat162float(h1.x), x.w - __bfloat162float(h1.y));
    uint2* dhi = (uint2*)(dst + r * KP2 + k);
    uint2* dlo = (uint2*)(dst + r * KP2 + 2048 + k);
    *dhi = make_uint2(hi0, hi1);
    *dlo = make_uint2(lo0, lo1);
}

// ---------------------------------------------------------------------------
// 2-plane bf16x3 NT GEMM, occupancy-2, NON-persistent (verified R12/R14 form).
// ---------------------------------------------------------------------------
#define PLANE3   8192
#define STAGE3   32768
#define NCH3     64

__global__ __launch_bounds__(256, 2)
void gemm_mma3_kernel(const __nv_bfloat16* __restrict__ A,
                      const __nv_bfloat16* __restrict__ B,
                      float* __restrict__ C, int ldc)
{
    extern __shared__ char smc[];
    const uint32_t sbase = smem_u32(smc);
    const int tid  = threadIdx.x;
    const int warp = tid >> 5, lane = tid & 31;
    const int wm = (warp & 3) * 32;
    const int wn = (warp >> 2) * 64;
    const int mBase = blockIdx.y * 128;
    const int nBase = blockIdx.x * 128;

    const int lrow = tid >> 1;
    const int lu0  = (tid & 1) * 2;

    const char* Ag = (const char*)A + (size_t)(mBase + lrow) * (KP2 * 2) + lu0 * 16;
    const char* Bg = (const char*)B + (size_t)(nBase + lrow) * (KP2 * 2) + lu0 * 16;

#define LOAD_STAGE3(stage, chunk) do {                                        \
    uint32_t _s = sbase + (stage) * STAGE3;                                   \
    size_t _go = (size_t)(chunk) * 64;                                        \
    _Pragma("unroll")                                                         \
    for (int _u = 0; _u < 2; _u++) {                                          \
        uint32_t _sw = SWZ64((uint32_t)(lrow * 64 + (lu0 + _u) * 16));        \
        CP_ASYNC16(_s + _sw,              Ag + _go + _u * 16);                \
        CP_ASYNC16(_s + PLANE3 + _sw,     Ag + 4096 + _go + _u * 16);         \
        CP_ASYNC16(_s + 2 * PLANE3 + _sw, Bg + _go + _u * 16);                \
        CP_ASYNC16(_s + 3 * PLANE3 + _sw, Bg + 4096 + _go + _u * 16);         \
    } } while (0)

    float acc[2][8][4];
    #pragma unroll
    for (int i = 0; i < 2; i++)
        #pragma unroll
        for (int j = 0; j < 8; j++)
            #pragma unroll
            for (int q = 0; q < 4; q++) acc[i][j][q] = 0.f;

    LOAD_STAGE3(0, 0); CP_COMMIT();
    LOAD_STAGE3(1, 1); CP_COMMIT();

    const uint32_t arow = wm + (lane & 15);
    const uint32_t acol16 = (lane >> 4) * 16;
    const uint32_t brow_lo = wn + (lane & 7) + ((lane >> 4) * 8);
    const uint32_t bcol16 = ((lane >> 3) & 1) * 16;

    int stage = 0;
    for (int it = 0; it < NCH3; it++) {
        CP_WAIT(1);
        __syncthreads();
        const uint32_t s0 = sbase + stage * STAGE3;

        #pragma unroll
        for (int ks = 0; ks < 2; ks++) {
            uint32_t aH0[4], aH1[4], aL0[4], aL1[4];
            uint32_t ao = arow * 64 + ks * 32 + acol16;
            uint32_t swa0 = SWZ64(ao), swa1 = SWZ64(ao + 16 * 64);
            ldsm_x4(aH0, s0 + swa0);
            ldsm_x4(aH1, s0 + swa1);
            ldsm_x4(aL0, s0 + PLANE3 + swa0);
            ldsm_x4(aL1, s0 + PLANE3 + swa1);
            #pragma unroll
            for (int nt = 0; nt < 4; nt++) {
                uint32_t bo = (brow_lo + nt * 16) * 64 + ks * 32 + bcol16;
                uint32_t swb = SWZ64(bo);
                uint32_t bH[4], bL[4];
                ldsm_x4(bH, s0 + 2 * PLANE3 + swb);
                ldsm_x4(bL, s0 + 3 * PLANE3 + swb);
                mma16816(acc[0][nt * 2],     aH0, &bH[0]);
                mma16816(acc[0][nt * 2 + 1], aH0, &bH[2]);
                mma16816(acc[1][nt * 2],     aH1, &bH[0]);
                mma16816(acc[1][nt * 2 + 1], aH1, &bH[2]);
                mma16816(acc[0][nt * 2],     aL0, &bH[0]);
                mma16816(acc[0][nt * 2 + 1], aL0, &bH[2]);
                mma16816(acc[1][nt * 2],     aL1, &bH[0]);
                mma16816(acc[1][nt * 2 + 1], aL1, &bH[2]);
                mma16816(acc[0][nt * 2],     aH0, &bL[0]);
                mma16816(acc[0][nt * 2 + 1], aH0, &bL[2]);
                mma16816(acc[1][nt * 2],     aH1, &bL[0]);
                mma16816(acc[1][nt * 2 + 1], aH1, &bL[2]);
            }
        }

        int nx = it + 2;
        if (nx < NCH3) {
            int ns = stage + 2; if (ns >= 3) ns -= 3;
            LOAD_STAGE3(ns, nx);
        }
        CP_COMMIT();
        if (++stage == 3) stage = 0;
    }
#undef LOAD_STAGE3

    const int r0 = mBase + wm + (lane >> 2);
    const int c0 = nBase + wn + (lane & 3) * 2;
    #pragma unroll
    for (int mt = 0; mt < 2; mt++) {
        #pragma unroll
        for (int nt = 0; nt < 8; nt++) {
            const int r = r0 + mt * 16;
            const int c = c0 + nt * 8;
            *(float2*)&C[(size_t)r * ldc + c]       = make_float2(acc[mt][nt][0], acc[mt][nt][1]);
            *(float2*)&C[(size_t)(r + 8) * ldc + c] = make_float2(acc[mt][nt][2], acc[mt][nt][3]);
        }
    }
}

// ---------------------------------------------------------------------------
// Fused RoPE + Q/K pack + cache scatter + V transpose/split. (unchanged)
// ---------------------------------------------------------------------------
#define QSCL 0.09016844335f   // D^-1/2 * log2(e)

__global__ __launch_bounds__(512)
void ropevt_kernel(const float* __restrict__ qkv,
                   const float* __restrict__ cosp,
                   const float* __restrict__ sinp,
                   const int* __restrict__ slots,
                   float* __restrict__ kc_out,
                   float* __restrict__ vc_out,
                   __nv_bfloat16* __restrict__ qpack,
                   __nv_bfloat16* __restrict__ kpack,
                   __nv_bfloat16* __restrict__ vt)
{
    __shared__ float tile[64][33];
    const int tid = threadIdx.x;
    const int t0 = blockIdx.x * 64;

    #pragma unroll 4
    for (int i = 0; i < 16; i++) {
        int idx = i * 512 + tid;
        int d = idx & 127, tl = idx >> 7;
        int t = t0 + tl;
        const float c = cosp[t * 128 + d];
        const float s = sinp[t * 128 + d];
        const float* row = qkv + (size_t)t * NQKV;

        #pragma unroll
        for (int h = 0; h < NHEADS; h++) {
            float x1 = row[h * DHEAD + d], x2 = row[h * DHEAD + d + 128];
            float y1 = (x1 * c - x2 * s) * QSCL;
            float y2 = (x2 * c + x1 * s) * QSCL;
            __nv_bfloat16 h1 = __float2bfloat16_rn(y1);
            __nv_bfloat16 h2 = __float2bfloat16_rn(y2);
            __nv_bfloat16* qp = qpack + ((size_t)(t * NHEADS + h) * 2) * DHEAD;
            qp[d] = h1; qp[d + 128] = h2;
            qp[DHEAD + d]       = __float2bfloat16_rn(y1 - __bfloat162float(h1));
            qp[DHEAD + d + 128] = __float2bfloat16_rn(y2 - __bfloat162float(h2));
        }
        {
            float x1 = row[NHEADS * DHEAD + d], x2 = row[NHEADS * DHEAD + d + 128];
            float y1 = x1 * c - x2 * s;
            float y2 = x2 * c + x1 * s;
            const int slot = slots[t];
            kc_out[(size_t)slot * DHEAD + d]       = y1;
            kc_out[(size_t)slot * DHEAD + 128 + d] = y2;
            __nv_bfloat16 h1 = __float2bfloat16_rn(y1);
            __nv_bfloat16 h2 = __float2bfloat16_rn(y2);
            __nv_bfloat16* kp = kpack + (size_t)t * 2 * DHEAD;
            kp[d] = h1; kp[d + 128] = h2;
            kp[DHEAD + d]       = __float2bfloat16_rn(y1 - __bfloat162float(h1));
            kp[DHEAD + d + 128] = __float2bfloat16_rn(y2 - __bfloat162float(h2));
        }
        {
            const int slot = slots[t];
            float v1 = row[(NHEADS + 1) * DHEAD + d], v2 = row[(NHEADS + 1) * DHEAD + d + 128];
            vc_out[(size_t)slot * DHEAD + d]       = v1;
            vc_out[(size_t)slot * DHEAD + 128 + d] = v2;
        }
    }

    for (int d0 = 0; d0 < DHEAD; d0 += 32) {
        __syncthreads();
        #pragma unroll
        for (int w = 0; w < 4; w++) {
            int lin = w * 512 + tid;
            int dl = lin & 31, tl = lin >> 5;
            tile[tl][dl] = qkv[(size_t)(t0 + tl) * NQKV + (NHEADS + 1) * DHEAD + d0 + dl];
        }
        __syncthreads();
        #pragma unroll
        for (int w = 0; w < 4; w++) {
            int lin = w * 512 + tid;
            int dl = lin >> 6, tl = lin & 63;
            float x = tile[tl][dl];
            __nv_bfloat16 hi = __float2bfloat16_rn(x);
            __nv_bfloat16 lo = __float2bfloat16_rn(x - __bfloat162float(hi));
            size_t base = (size_t)(d0 + dl) * T_TOK + t0 + tl;
            vt[base] = hi;
            vt[(size_t)DHEAD * T_TOK + base] = lo;
        }
    }
}

// ---------------------------------------------------------------------------
// Tensor-core flash attention (bf16x3, Q hoisted), PERSISTENT, max-free
// softmax (shift-invariant; exp2(s) cannot overflow fp32 for this problem),
// K double-buffered in the recycled Q-staging region. 2 CTA syncs/iter.
// smem: KA 64K | KB(=Q staging) 64K | V 64K | P 16K | redS 0.5K
// ---------------------------------------------------------------------------
#define KA_HI  0u
#define KB_HI  65536u
#define V_HI   131072u
#define V_LO   163840u
#define P_HI   196608u
#define P_LO   204800u
#define RED_S  212992u
#define ATTN_SMEM 213504
#define N_ATTN_TILES ((SEQ / 64) * NHEADS * 4)

__global__ __launch_bounds__(256, 1)
void attn_mma_kernel(const __nv_bfloat16* __restrict__ qpack,
                     const __nv_bfloat16* __restrict__ kpack,
                     const __nv_bfloat16* __restrict__ vpackT,
                     __nv_bfloat16* __restrict__ opack)
{
    extern __shared__ char smem[];
    const uint32_t sb = smem_u32(smem);
    float* smf = (float*)smem;

    const int tid  = threadIdx.x;
    const int warp = tid >> 5, lane = tid & 31;
    const int wm = warp & 3, wn = warp >> 2;

    const uint32_t arow   = (uint32_t)(wm * 16 + (lane & 15));
    const uint32_t acol16 = (uint32_t)((lane >> 4) * 16);
    const uint32_t brlo   = (uint32_t)((lane & 7) + ((lane >> 4) << 3));
    const uint32_t bcol16 = (uint32_t)(((lane >> 3) & 1) * 16);
    const int rbase = wm * 16 + (lane >> 2);

    for (int idx = blockIdx.x; idx < N_ATTN_TILES; idx += gridDim.x) {
        const int qb = (SEQ / 64 - 1) - (idx >> 5);   // descending qb blocks
        const int h  = (idx & 31) >> 2;
        const int b  = idx & 3;
        const int t0 = b * SEQ + qb * 64;

        // ---- prologue: Q -> KB (staging), K0 -> KA; one commit group
        #pragma unroll
        for (int p = 0; p < 2; p++) {
            #pragma unroll
            for (int i = 0; i < 8; i++) {
                int li = i * 256 + tid;
                int tl = li >> 5, c16 = li & 31;
                const char* src = (const char*)(qpack +
                    (((size_t)(t0 + tl) * NHEADS + h) * 2 + p) * DHEAD + c16 * 8);
                uint32_t dst = sb + KB_HI + p * 32768u +
                               (uint32_t)(c16 >> 3) * 8192u +
                               SWZ((uint32_t)(tl * 128 + (c16 & 7) * 16));
                CP_ASYNC16(dst, src);
            }
        }
        {
            int tk0 = b * SEQ;
            #pragma unroll
            for (int p = 0; p < 2; p++) {
                #pragma unroll
                for (int i = 0; i < 8; i++) {
                    int li = i * 256 + tid;
                    int tl = li >> 5, c16 = li & 31;
                    const char* src = (const char*)(kpack +
                        ((size_t)(tk0 + tl) * 2 + p) * DHEAD + c16 * 8);
                    uint32_t dst = sb + KA_HI + p * 32768u +
                                   (uint32_t)(c16 >> 3) * 8192u +
                                   SWZ((uint32_t)(tl * 128 + (c16 & 7) * 16));
                    CP_ASYNC16(dst, src);
                }
            }
        }
        CP_COMMIT();

        float O[16][4];
        #pragma unroll
        for (int i = 0; i < 16; i++)
            #pragma unroll
            for (int j = 0; j < 4; j++) O[i][j] = 0.f;
        float sumAcc0 = 0.f, sumAcc1 = 0.f;

        // hoist Q fragments from KB (dead after this; KB becomes K buffer 1)
        CP_WAIT(0);
        __syncthreads();
        uint32_t qf[2][16][4];
        #pragma unroll
        for (int p = 0; p < 2; p++)
            #pragma unroll
            for (int ks = 0; ks < 16; ks++) {
                uint32_t off = (uint32_t)(ks >> 2) * 8192u +
                               SWZ(arow * 128 + (ks & 3) * 32 + acol16);
                ldsm_x4(qf[p][ks], sb + KB_HI + p * 32768u + off);
            }

        for (int kt = 0; kt <= qb; kt++) {
            CP_WAIT(0);        // K(kt) complete (full-iteration window)
            __syncthreads();   // K visible; V buffer + P free (prev PV done)

            const int tkv = b * SEQ + kt * 64;
            // issue V(kt)
            #pragma unroll
            for (int p = 0; p < 2; p++) {
                #pragma unroll
                for (int i = 0; i < 8; i++) {
                    int li = i * 256 + tid;
                    int dl = li >> 3, c16 = li & 7;
                    const char* src = (const char*)(vpackT +
                        (size_t)p * DHEAD * T_TOK + (size_t)dl * T_TOK + tkv + c16 * 8);
                    uint32_t dst = sb + V_HI + p * 32768u +
                                   SWZ((uint32_t)(dl * 128 + c16 * 16));
                    CP_ASYNC16(dst, src);
                }
            }
            CP_COMMIT();
            // issue K(kt+1) into the other buffer (full iteration to load)
            if (kt < qb) {
                const int tk1 = b * SEQ + (kt + 1) * 64;
                const uint32_t kb1 = ((kt + 1) & 1) ? KB_HI : KA_HI;
                #pragma unroll
                for (int p = 0; p < 2; p++) {
                    #pragma unroll
                    for (int i = 0; i < 8; i++) {
                        int li = i * 256 + tid;
                        int tl = li >> 5, c16 = li & 31;
                        const char* src = (const char*)(kpack +
                            ((size_t)(tk1 + tl) * 2 + p) * DHEAD + c16 * 8);
                        uint32_t dst = sb + kb1 + p * 32768u +
                                       (uint32_t)(c16 >> 3) * 8192u +
                                       SWZ((uint32_t)(tl * 128 + (c16 & 7) * 16));
                        CP_ASYNC16(dst, src);
                    }
                }
                CP_COMMIT();
            }

            // ---- QK: S = Qhi.Khi + Qlo.Khi + Qhi.Klo
            const uint32_t kb0 = (kt & 1) ? KB_HI : KA_HI;
            float s[4][4];
            #pragma unroll
            for (int i = 0; i < 4; i++)
                #pragma unroll
                for (int j = 0; j < 4; j++) s[i][j] = 0.f;

            #pragma unroll
            for (int ks = 0; ks < 16; ks++) {
                const uint32_t blk = (uint32_t)(ks >> 2) * 8192u;
                #pragma unroll
                for (int nt = 0; nt < 2; nt++) {
                    uint32_t brow = (uint32_t)(wn * 32 + nt * 16) + brlo;
                    uint32_t swb = blk + SWZ(brow * 128 + (ks & 3) * 32 + bcol16);
                    uint32_t bH[4], bL[4];
                    ldsm_x4(bH, sb + kb0 + swb);
                    ldsm_x4(bL, sb + kb0 + 32768u + swb);
                    mma16816(s[nt * 2],     qf[0][ks], &bH[0]);
                    mma16816(s[nt * 2 + 1], qf[0][ks], &bH[2]);
                    mma16816(s[nt * 2],     qf[1][ks], &bH[0]);
                    mma16816(s[nt * 2 + 1], qf[1][ks], &bH[2]);
                    mma16816(s[nt * 2],     qf[0][ks], &bL[0]);
                    mma16816(s[nt * 2 + 1], qf[0][ks], &bL[2]);
                }
            }

            if (kt == qb) {
                #pragma unroll
                for (int nf = 0; nf < 4; nf++) {
                    int c = wn * 32 + nf * 8 + (lane & 3) * 2;
                    #pragma unroll
                    for (int half = 0; half < 2; half++) {
                        int r = rbase + half * 8;
                        if (c     > r) s[nf][half * 2]     = -1e30f;
                        if (c + 1 > r) s[nf][half * 2 + 1] = -1e30f;
                    }
                }
            }

            // ---- max-free softmax: p = exp2(s); sums accumulate in registers
            #pragma unroll
            for (int half = 0; half < 2; half++) {
                int r = rbase + half * 8;
                #pragma unroll
                for (int nf = 0; nf < 4; nf++) {
                    int c = wn * 32 + nf * 8 + (lane & 3) * 2;
                    float p0 = exp2f(s[nf][half * 2]);
                    float p1 = exp2f(s[nf][half * 2 + 1]);
                    if (half == 0) sumAcc0 += p0 + p1; else sumAcc1 += p0 + p1;
                    __nv_bfloat16 h0 = __float2bfloat16_rn(p0);
                    __nv_bfloat16 h1 = __float2bfloat16_rn(p1);
                    float l0 = p0 - __bfloat162float(h0);
                    float l1 = p1 - __bfloat162float(h1);
                    uint32_t off = SWZ((uint32_t)(r * 128 + c * 2));
                    uint16_t u0 = *(uint16_t*)&h0, u1 = *(uint16_t*)&h1;
                    *(uint32_t*)(smem + P_HI + off) = (uint32_t)u0 | ((uint32_t)u1 << 16);
                    *(uint32_t*)(smem + P_LO + off) = bf16pair(l0, l1);
                }
            }

            if (kt < qb) { CP_WAIT(1); }   // V(kt) done; K(kt+1) still in flight
            else         { CP_WAIT(0); }
            __syncthreads();               // V + P visible

            // ---- PV: O += Phi.Vhi + Plo.Vhi + Phi.Vlo
            #pragma unroll
            for (int ks = 0; ks < 4; ks++) {
                uint32_t aH[4], aL[4];
                uint32_t ao = SWZ(arow * 128 + ks * 32 + acol16);
                ldsm_x4(aH, sb + P_HI + ao);
                ldsm_x4(aL, sb + P_LO + ao);
                #pragma unroll
                for (int nt = 0; nt < 8; nt++) {
                    uint32_t brow = (uint32_t)(wn * 128 + nt * 16) + brlo;
                    uint32_t bo = SWZ(brow * 128 + ks * 32 + bcol16);
                    uint32_t bH[4], bL[4];
                    ldsm_x4(bH, sb + V_HI + bo);
                    ldsm_x4(bL, sb + V_LO + bo);
                    mma16816(O[nt * 2],     aH, &bH[0]);
                    mma16816(O[nt * 2 + 1], aH, &bH[2]);
                    mma16816(O[nt * 2],     aL, &bH[0]);
                    mma16816(O[nt * 2 + 1], aL, &bH[2]);
                    mma16816(O[nt * 2],     aH, &bL[0]);
                    mma16816(O[nt * 2 + 1], aH, &bL[2]);
                }
            }
        }

        // ---- epilogue: single row-sum reduction, normalize, write o operand
        sumAcc0 += __shfl_xor_sync(0xffffffffu, sumAcc0, 1);
        sumAcc0 += __shfl_xor_sync(0xffffffffu, sumAcc0, 2);
        sumAcc1 += __shfl_xor_sync(0xffffffffu, sumAcc1, 1);
        sumAcc1 += __shfl_xor_sync(0xffffffffu, sumAcc1, 2);
        if ((lane & 3) == 0) {
            smf[RED_S / 4 + wn * 64 + rbase]     = sumAcc0;
            smf[RED_S / 4 + wn * 64 + rbase + 8] = sumAcc1;
        }
        __syncthreads();
        float inv0 = 1.0f / (smf[RED_S / 4 + rbase]     + smf[RED_S / 4 + 64 + rbase]);
        float inv1 = 1.0f / (smf[RED_S / 4 + rbase + 8] + smf[RED_S / 4 + 64 + rbase + 8]);

        #pragma unroll
        for (int half = 0; half < 2; half++) {
            const int r = rbase + half * 8;
            const float inv = half ? inv1 : inv0;
            __nv_bfloat16* orow = opack + (size_t)(t0 + r) * KP2 + h * DHEAD;
            #pragma unroll
            for (int nt = 0; nt < 16; nt++) {
                int c = wn * 128 + nt * 8 + (lane & 3) * 2;
                float o0 = O[nt][half * 2]     * inv;
                float o1 = O[nt][half * 2 + 1] * inv;
                __nv_bfloat16 h0 = __float2bfloat16_rn(o0);
                __nv_bfloat16 h1 = __float2bfloat16_rn(o1);
                uint32_t hi = (uint32_t)(*(uint16_t*)&h0) | ((uint32_t)(*(uint16_t*)&h1) << 16);
                uint32_t lo = bf16pair(o0 - __bfloat162float(h0), o1 - __bfloat162float(h1));
                *(uint32_t*)(orow + c)        = hi;
                *(uint32_t*)(orow + 2048 + c) = lo;
            }
        }
        __syncthreads();   // guard before next tile rewrites smem
    }
}

// ---------------------------------------------------------------------------
// Launch
// ---------------------------------------------------------------------------
extern "C" void kernel_launch(void* const* d_in, const int* in_sizes, int n_in,
                              void* d_out, int out_size)
{
    (void)in_sizes; (void)n_in; (void)out_size;
    const float* hidden = (const float*)d_in[0];
    const float* cosp   = (const float*)d_in[1];
    const float* sinp   = (const float*)d_in[2];
    const int*   slots  = (const int*)d_in[3];
    const float* kc_in  = (const float*)d_in[4];
    const float* vc_in  = (const float*)d_in[5];
    const float* wqkv   = (const float*)d_in[6];
    const float* wo     = (const float*)d_in[7];

    float* out    = (float*)d_out;
    float* kc_out = out + (size_t)T_TOK * HIDD;
    float* vc_out = kc_out + (size_t)NSLOTS * DHEAD;

    float* qkv = nullptr;
    __nv_bfloat16 *pA = nullptr, *pB = nullptr, *qp = nullptr, *kp = nullptr, *vt = nullptr;
    cudaGetSymbolAddress((void**)&qkv, g_qkv);
    cudaGetSymbolAddress((void**)&pA,  g_packA);
    cudaGetSymbolAddress((void**)&pB,  g_packB);
    cudaGetSymbolAddress((void**)&qp,  g_qpack);
    cudaGetSymbolAddress((void**)&kp,  g_kpack);
    cudaGetSymbolAddress((void**)&vt,  g_vpackT);

    const int gemm_smem = 3 * STAGE3;   // 98304 -> 2 CTAs/SM
    cudaFuncSetAttribute(gemm_mma3_kernel,
                         cudaFuncAttributeMaxDynamicSharedMemorySize, gemm_smem);
    cudaFuncSetAttribute(attn_mma_kernel,
                         cudaFuncAttributeMaxDynamicSharedMemorySize, ATTN_SMEM);

    // #1: fused cache passthrough
    {
        long n = (long)NSLOTS * DHEAD / 4;
        cachecopy_kernel<<<(unsigned)((n + 255) / 256), 256>>>(
            (const float4*)kc_in, (const float4*)vc_in,
            (float4*)kc_out, (float4*)vc_out);
    }

    // #2,#3: pack QKV-proj operands; #4: QKV projection
    {
        long tA4 = (long)T_TOK * HIDD / 4;
        long tB4 = (long)NQKV * HIDD / 4;
        pack2_kernel<<<(unsigned)((tA4 + 255) / 256), 256>>>((const float4*)hidden, pA, tA4);
        pack2_kernel<<<(unsigned)((tB4 + 255) / 256), 256>>>((const float4*)wqkv,   pB, tB4);
        gemm_mma3_kernel<<<dim3(NQKV / 128, T_TOK / 128), 256, gemm_smem>>>(pA, pB, qkv, NQKV);
    }

    // #5: fused RoPE + packs + cache scatter + V transpose
    ropevt_kernel<<<T_TOK / 64, 512>>>(qkv, cosp, sinp, slots, kc_out, vc_out, qp, kp, vt);

    // #6: persistent max-free tensor-core flash attention (148 CTAs)
    attn_mma_kernel<<<148, 256, ATTN_SMEM>>>(qp, kp, vt, pA);

    // #7: pack O-proj weights; #8: output projection
    {
        long tB4 = (long)HIDD * HIDD / 4;
        pack2_kernel<<<(unsigned)((tB4 + 255) / 256), 256>>>((const float4*)wo, pB, tB4);
        gemm_mma3_kernel<<<dim3(HIDD / 128, T_TOK / 128), 256, gemm_smem>>>(pA, pB, out, HIDD);
    }
}

// round 16
// speedup vs baseline: 1.1244x; 1.0384x over previous
#include <cuda_runtime.h>
#include <cuda_bf16.h>
#include <cstdint>
#include <cstddef>

#define T_TOK   8192
#define HIDD    2048
#define NQKV    2560
#define DHEAD   256
#define NHEADS  8
#define SEQ     2048
#define NSLOTS  16384
#define KP2     4096        // 2-plane row: [hi 2048 | lo 2048]

// ---------------- scratch ----------------
__device__ float g_qkv[(size_t)T_TOK * NQKV];
__device__ __nv_bfloat16 g_packA[(size_t)T_TOK * KP2];
__device__ __nv_bfloat16 g_packB[(size_t)NQKV * KP2];
__device__ __nv_bfloat16 g_qpack[(size_t)T_TOK * NHEADS * 2 * DHEAD];
__device__ __nv_bfloat16 g_kpack[(size_t)T_TOK * 2 * DHEAD];
__device__ __nv_bfloat16 g_vpackT[(size_t)2 * DHEAD * T_TOK];
__device__ int g_tileCtr;

__device__ __forceinline__ uint32_t smem_u32(const void* p) {
    uint32_t a;
    asm("{ .reg .u64 t; cvta.to.shared.u64 t, %1; cvt.u32.u64 %0, t; }" : "=r"(a) : "l"(p));
    return a;
}

#define SWZ(o)   ((o) ^ (((o) >> 3) & 0x70))   // 128B rows
#define SWZ64(o) ((o) ^ (((o) >> 3) & 0x30))   // 64B rows

#define CP_ASYNC16(dst, src) \
    asm volatile("cp.async.cg.shared.global [%0], [%1], 16;" :: "r"(dst), "l"(src))
#define CP_COMMIT() asm volatile("cp.async.commit_group;" ::: "memory")
#define CP_WAIT(n)  asm volatile("cp.async.wait_group %0;" :: "n"(n) : "memory")

__device__ __forceinline__ void ldsm_x4(uint32_t* r, uint32_t addr) {
    asm volatile("ldmatrix.sync.aligned.m8n8.x4.shared.b16 {%0,%1,%2,%3}, [%4];"
        : "=r"(r[0]), "=r"(r[1]), "=r"(r[2]), "=r"(r[3]) : "r"(addr));
}

__device__ __forceinline__ void mma16816(float* d, const uint32_t* a, const uint32_t* b) {
    asm volatile(
        "mma.sync.aligned.m16n8k16.row.col.f32.bf16.bf16.f32 "
        "{%0,%1,%2,%3}, {%4,%5,%6,%7}, {%8,%9}, {%0,%1,%2,%3};"
        : "+f"(d[0]), "+f"(d[1]), "+f"(d[2]), "+f"(d[3])
        : "r"(a[0]), "r"(a[1]), "r"(a[2]), "r"(a[3]), "r"(b[0]), "r"(b[1]));
}

__device__ __forceinline__ uint32_t bf16pair(float a, float b) {
    __nv_bfloat16 ha = __float2bfloat16_rn(a), hb = __float2bfloat16_rn(b);
    uint16_t ua = *(uint16_t*)&ha, ub = *(uint16_t*)&hb;
    return (uint32_t)ua | ((uint32_t)ub << 16);
}

// ---------------------------------------------------------------------------
// Fused KV-cache passthrough copy.
// ---------------------------------------------------------------------------
__global__ void cachecopy_kernel(const float4* __restrict__ kc_in,
                                 const float4* __restrict__ vc_in,
                                 float4* __restrict__ kc_out,
                                 float4* __restrict__ vc_out)
{
    const long n = (long)NSLOTS * DHEAD / 4;
    long i = (long)blockIdx.x * blockDim.x + threadIdx.x;
    if (i < n) {
        kc_out[i] = kc_in[i];
        vc_out[i] = vc_in[i];
    }
}

// ---------------------------------------------------------------------------
// Pack fp32 -> 2-plane bf16 [hi | lo], vectorized.
// ---------------------------------------------------------------------------
__global__ void pack2_kernel(const float4* __restrict__ src,
                             __nv_bfloat16* __restrict__ dst, long total4)
{
    long idx = (long)blockIdx.x * blockDim.x + threadIdx.x;
    if (idx >= total4) return;
    float4 x = src[idx];
    long e = idx * 4;
    int k = (int)(e & 2047);
    long r = e >> 11;
    uint32_t hi0 = bf16pair(x.x, x.y);
    uint32_t hi1 = bf16pair(x.z, x.w);
    __nv_bfloat162 h0 = *(__nv_bfloat162*)&hi0;
    __nv_bfloat162 h1 = *(__nv_bfloat162*)&hi1;
    uint32_t lo0 = bf16pair(x.x - __bfloat162float(h0.x), x.y - __bfloat162float(h0.y));
    uint32_t lo1 = bf16pair(x.z - __bfloat162float(h1.x), x.w - __bfloat162float(h1.y));
    uint2* dhi = (uint2*)(dst + r * KP2 + k);
    uint2* dlo = (uint2*)(dst + r * KP2 + 2048 + k);
    *dhi = make_uint2(hi0, hi1);
    *dlo = make_uint2(lo0, lo1);
}

// ---------------------------------------------------------------------------
// 2-plane bf16x3 NT GEMM, occupancy-2, NON-persistent (verified form).
// ---------------------------------------------------------------------------
#define PLANE3   8192
#define STAGE3   32768
#define NCH3     64

__global__ __launch_bounds__(256, 2)
void gemm_mma3_kernel(const __nv_bfloat16* __restrict__ A,
                      const __nv_bfloat16* __restrict__ B,
                      float* __restrict__ C, int ldc)
{
    extern __shared__ char smc[];
    const uint32_t sbase = smem_u32(smc);
    const int tid  = threadIdx.x;
    const int warp = tid >> 5, lane = tid & 31;
    const int wm = (warp & 3) * 32;
    const int wn = (warp >> 2) * 64;
    const int mBase = blockIdx.y * 128;
    const int nBase = blockIdx.x * 128;

    const int lrow = tid >> 1;
    const int lu0  = (tid & 1) * 2;

    const char* Ag = (const char*)A + (size_t)(mBase + lrow) * (KP2 * 2) + lu0 * 16;
    const char* Bg = (const char*)B + (size_t)(nBase + lrow) * (KP2 * 2) + lu0 * 16;

#define LOAD_STAGE3(stage, chunk) do {                                        \
    uint32_t _s = sbase + (stage) * STAGE3;                                   \
    size_t _go = (size_t)(chunk) * 64;                                        \
    _Pragma("unroll")                                                         \
    for (int _u = 0; _u < 2; _u++) {                                          \
        uint32_t _sw = SWZ64((uint32_t)(lrow * 64 + (lu0 + _u) * 16));        \
        CP_ASYNC16(_s + _sw,              Ag + _go + _u * 16);                \
        CP_ASYNC16(_s + PLANE3 + _sw,     Ag + 4096 + _go + _u * 16);         \
        CP_ASYNC16(_s + 2 * PLANE3 + _sw, Bg + _go + _u * 16);                \
        CP_ASYNC16(_s + 3 * PLANE3 + _sw, Bg + 4096 + _go + _u * 16);         \
    } } while (0)

    float acc[2][8][4];
    #pragma unroll
    for (int i = 0; i < 2; i++)
        #pragma unroll
        for (int j = 0; j < 8; j++)
            #pragma unroll
            for (int q = 0; q < 4; q++) acc[i][j][q] = 0.f;

    LOAD_STAGE3(0, 0); CP_COMMIT();
    LOAD_STAGE3(1, 1); CP_COMMIT();

    const uint32_t arow = wm + (lane & 15);
    const uint32_t acol16 = (lane >> 4) * 16;
    const uint32_t brow_lo = wn + (lane & 7) + ((lane >> 4) * 8);
    const uint32_t bcol16 = ((lane >> 3) & 1) * 16;

    int stage = 0;
    for (int it = 0; it < NCH3; it++) {
        CP_WAIT(1);
        __syncthreads();
        const uint32_t s0 = sbase + stage * STAGE3;

        #pragma unroll
        for (int ks = 0; ks < 2; ks++) {
            uint32_t aH0[4], aH1[4], aL0[4], aL1[4];
            uint32_t ao = arow * 64 + ks * 32 + acol16;
            uint32_t swa0 = SWZ64(ao), swa1 = SWZ64(ao + 16 * 64);
            ldsm_x4(aH0, s0 + swa0);
            ldsm_x4(aH1, s0 + swa1);
            ldsm_x4(aL0, s0 + PLANE3 + swa0);
            ldsm_x4(aL1, s0 + PLANE3 + swa1);
            #pragma unroll
            for (int nt = 0; nt < 4; nt++) {
                uint32_t bo = (brow_lo + nt * 16) * 64 + ks * 32 + bcol16;
                uint32_t swb = SWZ64(bo);
                uint32_t bH[4], bL[4];
                ldsm_x4(bH, s0 + 2 * PLANE3 + swb);
                ldsm_x4(bL, s0 + 3 * PLANE3 + swb);
                mma16816(acc[0][nt * 2],     aH0, &bH[0]);
                mma16816(acc[0][nt * 2 + 1], aH0, &bH[2]);
                mma16816(acc[1][nt * 2],     aH1, &bH[0]);
                mma16816(acc[1][nt * 2 + 1], aH1, &bH[2]);
                mma16816(acc[0][nt * 2],     aL0, &bH[0]);
                mma16816(acc[0][nt * 2 + 1], aL0, &bH[2]);
                mma16816(acc[1][nt * 2],     aL1, &bH[0]);
                mma16816(acc[1][nt * 2 + 1], aL1, &bH[2]);
                mma16816(acc[0][nt * 2],     aH0, &bL[0]);
                mma16816(acc[0][nt * 2 + 1], aH0, &bL[2]);
                mma16816(acc[1][nt * 2],     aH1, &bL[0]);
                mma16816(acc[1][nt * 2 + 1], aH1, &bL[2]);
            }
        }

        int nx = it + 2;
        if (nx < NCH3) {
            int ns = stage + 2; if (ns >= 3) ns -= 3;
            LOAD_STAGE3(ns, nx);
        }
        CP_COMMIT();
        if (++stage == 3) stage = 0;
    }
#undef LOAD_STAGE3

    const int r0 = mBase + wm + (lane >> 2);
    const int c0 = nBase + wn + (lane & 3) * 2;
    #pragma unroll
    for (int mt = 0; mt < 2; mt++) {
        #pragma unroll
        for (int nt = 0; nt < 8; nt++) {
            const int r = r0 + mt * 16;
            const int c = c0 + nt * 8;
            *(float2*)&C[(size_t)r * ldc + c]       = make_float2(acc[mt][nt][0], acc[mt][nt][1]);
            *(float2*)&C[(size_t)(r + 8) * ldc + c] = make_float2(acc[mt][nt][2], acc[mt][nt][3]);
        }
    }
}

// ---------------------------------------------------------------------------
// Fused RoPE + Q/K pack + cache scatter + V transpose/split.
// Also resets the attention tile dispenser (runs before attention).
// ---------------------------------------------------------------------------
#define QSCL 0.09016844335f   // D^-1/2 * log2(e)

__global__ __launch_bounds__(512)
void ropevt_kernel(const float* __restrict__ qkv,
                   const float* __restrict__ cosp,
                   const float* __restrict__ sinp,
                   const int* __restrict__ slots,
                   float* __restrict__ kc_out,
                   float* __restrict__ vc_out,
                   __nv_bfloat16* __restrict__ qpack,
                   __nv_bfloat16* __restrict__ kpack,
                   __nv_bfloat16* __restrict__ vt)
{
    __shared__ float tile[64][33];
    const int tid = threadIdx.x;
    const int t0 = blockIdx.x * 64;

    if (blockIdx.x == 0 && tid == 0) g_tileCtr = 0;

    #pragma unroll 4
    for (int i = 0; i < 16; i++) {
        int idx = i * 512 + tid;
        int d = idx & 127, tl = idx >> 7;
        int t = t0 + tl;
        const float c = cosp[t * 128 + d];
        const float s = sinp[t * 128 + d];
        const float* row = qkv + (size_t)t * NQKV;

        #pragma unroll
        for (int h = 0; h < NHEADS; h++) {
            float x1 = row[h * DHEAD + d], x2 = row[h * DHEAD + d + 128];
            float y1 = (x1 * c - x2 * s) * QSCL;
            float y2 = (x2 * c + x1 * s) * QSCL;
            __nv_bfloat16 h1 = __float2bfloat16_rn(y1);
            __nv_bfloat16 h2 = __float2bfloat16_rn(y2);
            __nv_bfloat16* qp = qpack + ((size_t)(t * NHEADS + h) * 2) * DHEAD;
            qp[d] = h1; qp[d + 128] = h2;
            qp[DHEAD + d]       = __float2bfloat16_rn(y1 - __bfloat162float(h1));
            qp[DHEAD + d + 128] = __float2bfloat16_rn(y2 - __bfloat162float(h2));
        }
        {
            float x1 = row[NHEADS * DHEAD + d], x2 = row[NHEADS * DHEAD + d + 128];
            float y1 = x1 * c - x2 * s;
            float y2 = x2 * c + x1 * s;
            const int slot = slots[t];
            kc_out[(size_t)slot * DHEAD + d]       = y1;
            kc_out[(size_t)slot * DHEAD + 128 + d] = y2;
            __nv_bfloat16 h1 = __float2bfloat16_rn(y1);
            __nv_bfloat16 h2 = __float2bfloat16_rn(y2);
            __nv_bfloat16* kp = kpack + (size_t)t * 2 * DHEAD;
            kp[d] = h1; kp[d + 128] = h2;
            kp[DHEAD + d]       = __float2bfloat16_rn(y1 - __bfloat162float(h1));
            kp[DHEAD + d + 128] = __float2bfloat16_rn(y2 - __bfloat162float(h2));
        }
        {
            const int slot = slots[t];
            float v1 = row[(NHEADS + 1) * DHEAD + d], v2 = row[(NHEADS + 1) * DHEAD + d + 128];
            vc_out[(size_t)slot * DHEAD + d]       = v1;
            vc_out[(size_t)slot * DHEAD + 128 + d] = v2;
        }
    }

    for (int d0 = 0; d0 < DHEAD; d0 += 32) {
        __syncthreads();
        #pragma unroll
        for (int w = 0; w < 4; w++) {
            int lin = w * 512 + tid;
            int dl = lin & 31, tl = lin >> 5;
            tile[tl][dl] = qkv[(size_t)(t0 + tl) * NQKV + (NHEADS + 1) * DHEAD + d0 + dl];
        }
        __syncthreads();
        #pragma unroll
        for (int w = 0; w < 4; w++) {
            int lin = w * 512 + tid;
            int dl = lin >> 6, tl = lin & 63;
            float x = tile[tl][dl];
            __nv_bfloat16 hi = __float2bfloat16_rn(x);
            __nv_bfloat16 lo = __float2bfloat16_rn(x - __bfloat162float(hi));
            size_t base = (size_t)(d0 + dl) * T_TOK + t0 + tl;
            vt[base] = hi;
            vt[(size_t)DHEAD * T_TOK + base] = lo;
        }
    }
}

// ---------------------------------------------------------------------------
// Tensor-core flash attention (bf16x3, Q hoisted), PERSISTENT with DYNAMIC
// tile dispenser (LPT: tiles pre-sorted longest-first). Max-free softmax,
// K double-buffered in the recycled Q-staging region. 2 CTA syncs/iter.
// smem: KA 64K | KB(=Q staging) 64K | V 64K | P 16K | redS 0.5K | tileIdx
// ---------------------------------------------------------------------------
#define KA_HI  0u
#define KB_HI  65536u
#define V_HI   131072u
#define V_LO   163840u
#define P_HI   196608u
#define P_LO   204800u
#define RED_S  212992u
#define TIDX   213504u
#define ATTN_SMEM 213632
#define N_ATTN_TILES ((SEQ / 64) * NHEADS * 4)

__global__ __launch_bounds__(256, 1)
void attn_mma_kernel(const __nv_bfloat16* __restrict__ qpack,
                     const __nv_bfloat16* __restrict__ kpack,
                     const __nv_bfloat16* __restrict__ vpackT,
                     __nv_bfloat16* __restrict__ opack)
{
    extern __shared__ char smem[];
    const uint32_t sb = smem_u32(smem);
    float* smf = (float*)smem;
    int* tix = (int*)(smem + TIDX);

    const int tid  = threadIdx.x;
    const int warp = tid >> 5, lane = tid & 31;
    const int wm = warp & 3, wn = warp >> 2;

    const uint32_t arow   = (uint32_t)(wm * 16 + (lane & 15));
    const uint32_t acol16 = (uint32_t)((lane >> 4) * 16);
    const uint32_t brlo   = (uint32_t)((lane & 7) + ((lane >> 4) << 3));
    const uint32_t bcol16 = (uint32_t)(((lane >> 3) & 1) * 16);
    const int rbase = wm * 16 + (lane >> 2);

    while (true) {
        // ---- dynamic tile grab (LPT order via descending-qb index map)
        if (tid == 0) *tix = atomicAdd(&g_tileCtr, 1);
        __syncthreads();
        const int idx = *tix;
        if (idx >= N_ATTN_TILES) break;

        const int qb = (SEQ / 64 - 1) - (idx >> 5);   // descending qb blocks
        const int h  = (idx & 31) >> 2;
        const int b  = idx & 3;
        const int t0 = b * SEQ + qb * 64;

        // ---- prologue: Q -> KB (staging), K0 -> KA; one commit group
        #pragma unroll
        for (int p = 0; p < 2; p++) {
            #pragma unroll
            for (int i = 0; i < 8; i++) {
                int li = i * 256 + tid;
                int tl = li >> 5, c16 = li & 31;
                const char* src = (const char*)(qpack +
                    (((size_t)(t0 + tl) * NHEADS + h) * 2 + p) * DHEAD + c16 * 8);
                uint32_t dst = sb + KB_HI + p * 32768u +
                               (uint32_t)(c16 >> 3) * 8192u +
                               SWZ((uint32_t)(tl * 128 + (c16 & 7) * 16));
                CP_ASYNC16(dst, src);
            }
        }
        {
            int tk0 = b * SEQ;
            #pragma unroll
            for (int p = 0; p < 2; p++) {
                #pragma unroll
                for (int i = 0; i < 8; i++) {
                    int li = i * 256 + tid;
                    int tl = li >> 5, c16 = li & 31;
                    const char* src = (const char*)(kpack +
                        ((size_t)(tk0 + tl) * 2 + p) * DHEAD + c16 * 8);
                    uint32_t dst = sb + KA_HI + p * 32768u +
                                   (uint32_t)(c16 >> 3) * 8192u +
                                   SWZ((uint32_t)(tl * 128 + (c16 & 7) * 16));
                    CP_ASYNC16(dst, src);
                }
            }
        }
        CP_COMMIT();

        float O[16][4];
        #pragma unroll
        for (int i = 0; i < 16; i++)
            #pragma unroll
            for (int j = 0; j < 4; j++) O[i][j] = 0.f;
        float sumAcc0 = 0.f, sumAcc1 = 0.f;

        // hoist Q fragments from KB (dead after this; KB becomes K buffer 1)
        CP_WAIT(0);
        __syncthreads();
        uint32_t qf[2][16][4];
        #pragma unroll
        for (int p = 0; p < 2; p++)
            #pragma unroll
            for (int ks = 0; ks < 16; ks++) {
                uint32_t off = (uint32_t)(ks >> 2) * 8192u +
                               SWZ(arow * 128 + (ks & 3) * 32 + acol16);
                ldsm_x4(qf[p][ks], sb + KB_HI + p * 32768u + off);
            }

        for (int kt = 0; kt <= qb; kt++) {
            CP_WAIT(0);        // K(kt) complete (full-iteration window)
            __syncthreads();   // K visible; V buffer + P free (prev PV done)

            const int tkv = b * SEQ + kt * 64;
            // issue V(kt)
            #pragma unroll
            for (int p = 0; p < 2; p++) {
                #pragma unroll
                for (int i = 0; i < 8; i++) {
                    int li = i * 256 + tid;
                    int dl = li >> 3, c16 = li & 7;
                    const char* src = (const char*)(vpackT +
                        (size_t)p * DHEAD * T_TOK + (size_t)dl * T_TOK + tkv + c16 * 8);
                    uint32_t dst = sb + V_HI + p * 32768u +
                                   SWZ((uint32_t)(dl * 128 + c16 * 16));
                    CP_ASYNC16(dst, src);
                }
            }
            CP_COMMIT();
            // issue K(kt+1) into the other buffer (full iteration to load)
            if (kt < qb) {
                const int tk1 = b * SEQ + (kt + 1) * 64;
                const uint32_t kb1 = ((kt + 1) & 1) ? KB_HI : KA_HI;
                #pragma unroll
                for (int p = 0; p < 2; p++) {
                    #pragma unroll
                    for (int i = 0; i < 8; i++) {
                        int li = i * 256 + tid;
                        int tl = li >> 5, c16 = li & 31;
                        const char* src = (const char*)(kpack +
                            ((size_t)(tk1 + tl) * 2 + p) * DHEAD + c16 * 8);
                        uint32_t dst = sb + kb1 + p * 32768u +
                                       (uint32_t)(c16 >> 3) * 8192u +
                                       SWZ((uint32_t)(tl * 128 + (c16 & 7) * 16));
                        CP_ASYNC16(dst, src);
                    }
                }
                CP_COMMIT();
            }

            // ---- QK: S = Qhi.Khi + Qlo.Khi + Qhi.Klo
            const uint32_t kb0 = (kt & 1) ? KB_HI : KA_HI;
            float s[4][4];
            #pragma unroll
            for (int i = 0; i < 4; i++)
                #pragma unroll
                for (int j = 0; j < 4; j++) s[i][j] = 0.f;

            #pragma unroll
            for (int ks = 0; ks < 16; ks++) {
                const uint32_t blk = (uint32_t)(ks >> 2) * 8192u;
                #pragma unroll
                for (int nt = 0; nt < 2; nt++) {
                    uint32_t brow = (uint32_t)(wn * 32 + nt * 16) + brlo;
                    uint32_t swb = blk + SWZ(brow * 128 + (ks & 3) * 32 + bcol16);
                    uint32_t bH[4], bL[4];
                    ldsm_x4(bH, sb + kb0 + swb);
                    ldsm_x4(bL, sb + kb0 + 32768u + swb);
                    mma16816(s[nt * 2],     qf[0][ks], &bH[0]);
                    mma16816(s[nt * 2 + 1], qf[0][ks], &bH[2]);
                    mma16816(s[nt * 2],     qf[1][ks], &bH[0]);
                    mma16816(s[nt * 2 + 1], qf[1][ks], &bH[2]);
                    mma16816(s[nt * 2],     qf[0][ks], &bL[0]);
                    mma16816(s[nt * 2 + 1], qf[0][ks], &bL[2]);
                }
            }

            if (kt == qb) {
                #pragma unroll
                for (int nf = 0; nf < 4; nf++) {
                    int c = wn * 32 + nf * 8 + (lane & 3) * 2;
                    #pragma unroll
                    for (int half = 0; half < 2; half++) {
                        int r = rbase + half * 8;
                        if (c     > r) s[nf][half * 2]     = -1e30f;
                        if (c + 1 > r) s[nf][half * 2 + 1] = -1e30f;
                    }
                }
            }

            // ---- max-free softmax: p = exp2(s); sums accumulate in registers
            #pragma unroll
            for (int half = 0; half < 2; half++) {
                int r = rbase + half * 8;
                #pragma unroll
                for (int nf = 0; nf < 4; nf++) {
                    int c = wn * 32 + nf * 8 + (lane & 3) * 2;
                    float p0 = exp2f(s[nf][half * 2]);
                    float p1 = exp2f(s[nf][half * 2 + 1]);
                    if (half == 0) sumAcc0 += p0 + p1; else sumAcc1 += p0 + p1;
                    __nv_bfloat16 h0 = __float2bfloat16_rn(p0);
                    __nv_bfloat16 h1 = __float2bfloat16_rn(p1);
                    float l0 = p0 - __bfloat162float(h0);
                    float l1 = p1 - __bfloat162float(h1);
                    uint32_t off = SWZ((uint32_t)(r * 128 + c * 2));
                    uint16_t u0 = *(uint16_t*)&h0, u1 = *(uint16_t*)&h1;
                    *(uint32_t*)(smem + P_HI + off) = (uint32_t)u0 | ((uint32_t)u1 << 16);
                    *(uint32_t*)(smem + P_LO + off) = bf16pair(l0, l1);
                }
            }

            if (kt < qb) { CP_WAIT(1); }   // V(kt) done; K(kt+1) still in flight
            else         { CP_WAIT(0); }
            __syncthreads();               // V + P visible

            // ---- PV: O += Phi.Vhi + Plo.Vhi + Phi.Vlo
            #pragma unroll
            for (int ks = 0; ks < 4; ks++) {
                uint32_t aH[4], aL[4];
                uint32_t ao = SWZ(arow * 128 + ks * 32 + acol16);
                ldsm_x4(aH, sb + P_HI + ao);
                ldsm_x4(aL, sb + P_LO + ao);
                #pragma unroll
                for (int nt = 0; nt < 8; nt++) {
                    uint32_t brow = (uint32_t)(wn * 128 + nt * 16) + brlo;
                    uint32_t bo = SWZ(brow * 128 + ks * 32 + bcol16);
                    uint32_t bH[4], bL[4];
                    ldsm_x4(bH, sb + V_HI + bo);
                    ldsm_x4(bL, sb + V_LO + bo);
                    mma16816(O[nt * 2],     aH, &bH[0]);
                    mma16816(O[nt * 2 + 1], aH, &bH[2]);
                    mma16816(O[nt * 2],     aL, &bH[0]);
                    mma16816(O[nt * 2 + 1], aL, &bH[2]);
                    mma16816(O[nt * 2],     aH, &bL[0]);
                    mma16816(O[nt * 2 + 1], aH, &bL[2]);
                }
            }
        }

        // ---- epilogue: single row-sum reduction, normalize, write o operand
        sumAcc0 += __shfl_xor_sync(0xffffffffu, sumAcc0, 1);
        sumAcc0 += __shfl_xor_sync(0xffffffffu, sumAcc0, 2);
        sumAcc1 += __shfl_xor_sync(0xffffffffu, sumAcc1, 1);
        sumAcc1 += __shfl_xor_sync(0xffffffffu, sumAcc1, 2);
        if ((lane & 3) == 0) {
            smf[RED_S / 4 + wn * 64 + rbase]     = sumAcc0;
            smf[RED_S / 4 + wn * 64 + rbase + 8] = sumAcc1;
        }
        __syncthreads();
        float inv0 = 1.0f / (smf[RED_S / 4 + rbase]     + smf[RED_S / 4 + 64 + rbase]);
        float inv1 = 1.0f / (smf[RED_S / 4 + rbase + 8] + smf[RED_S / 4 + 64 + rbase + 8]);

        #pragma unroll
        for (int half = 0; half < 2; half++) {
            const int r = rbase + half * 8;
            const float inv = half ? inv1 : inv0;
            __nv_bfloat16* orow = opack + (size_t)(t0 + r) * KP2 + h * DHEAD;
            #pragma unroll
            for (int nt = 0; nt < 16; nt++) {
                int c = wn * 128 + nt * 8 + (lane & 3) * 2;
                float o0 = O[nt][half * 2]     * inv;
                float o1 = O[nt][half * 2 + 1] * inv;
                __nv_bfloat16 h0 = __float2bfloat16_rn(o0);
                __nv_bfloat16 h1 = __float2bfloat16_rn(o1);
                uint32_t hi = (uint32_t)(*(uint16_t*)&h0) | ((uint32_t)(*(uint16_t*)&h1) << 16);
                uint32_t lo = bf16pair(o0 - __bfloat162float(h0), o1 - __bfloat162float(h1));
                *(uint32_t*)(orow + c)        = hi;
                *(uint32_t*)(orow + 2048 + c) = lo;
            }
        }
        __syncthreads();   // guard before next tile rewrites smem / tix
    }
}

// ---------------------------------------------------------------------------
// Launch
// ---------------------------------------------------------------------------
extern "C" void kernel_launch(void* const* d_in, const int* in_sizes, int n_in,
                              void* d_out, int out_size)
{
    (void)in_sizes; (void)n_in; (void)out_size;
    const float* hidden = (const float*)d_in[0];
    const float* cosp   = (const float*)d_in[1];
    const float* sinp   = (const float*)d_in[2];
    const int*   slots  = (const int*)d_in[3];
    const float* kc_in  = (const float*)d_in[4];
    const float* vc_in  = (const float*)d_in[5];
    const float* wqkv   = (const float*)d_in[6];
    const float* wo     = (const float*)d_in[7];

    float* out    = (float*)d_out;
    float* kc_out = out + (size_t)T_TOK * HIDD;
    float* vc_out = kc_out + (size_t)NSLOTS * DHEAD;

    float* qkv = nullptr;
    __nv_bfloat16 *pA = nullptr, *pB = nullptr, *qp = nullptr, *kp = nullptr, *vt = nullptr;
    cudaGetSymbolAddress((void**)&qkv, g_qkv);
    cudaGetSymbolAddress((void**)&pA,  g_packA);
    cudaGetSymbolAddress((void**)&pB,  g_packB);
    cudaGetSymbolAddress((void**)&qp,  g_qpack);
    cudaGetSymbolAddress((void**)&kp,  g_kpack);
    cudaGetSymbolAddress((void**)&vt,  g_vpackT);

    const int gemm_smem = 3 * STAGE3;   // 98304 -> 2 CTAs/SM
    cudaFuncSetAttribute(gemm_mma3_kernel,
                         cudaFuncAttributeMaxDynamicSharedMemorySize, gemm_smem);
    cudaFuncSetAttribute(attn_mma_kernel,
                         cudaFuncAttributeMaxDynamicSharedMemorySize, ATTN_SMEM);

    // #1: fused cache passthrough
    {
        long n = (long)NSLOTS * DHEAD / 4;
        cachecopy_kernel<<<(unsigned)((n + 255) / 256), 256>>>(
            (const float4*)kc_in, (const float4*)vc_in,
            (float4*)kc_out, (float4*)vc_out);
    }

    // #2,#3: pack QKV-proj operands; #4: QKV projection
    {
        long tA4 = (long)T_TOK * HIDD / 4;
        long tB4 = (long)NQKV * HIDD / 4;
        pack2_kernel<<<(unsigned)((tA4 + 255) / 256), 256>>>((const float4*)hidden, pA, tA4);
        pack2_kernel<<<(unsigned)((tB4 + 255) / 256), 256>>>((const float4*)wqkv,   pB, tB4);
        gemm_mma3_kernel<<<dim3(NQKV / 128, T_TOK / 128), 256, gemm_smem>>>(pA, pB, qkv, NQKV);
    }

    // #5: fused RoPE + packs + cache scatter + V transpose (+ ctr reset)
    ropevt_kernel<<<T_TOK / 64, 512>>>(qkv, cosp, sinp, slots, kc_out, vc_out, qp, kp, vt);

    // #6: persistent dynamic-scheduled tensor-core flash attention (148 CTAs)
    attn_mma_kernel<<<148, 256, ATTN_SMEM>>>(qp, kp, vt, pA);

    // #7: pack O-proj weights; #8: output projection
    {
        long tB4 = (long)HIDD * HIDD / 4;
        pack2_kernel<<<(unsigned)((tB4 + 255) / 256), 256>>>((const float4*)wo, pB, tB4);
        gemm_mma3_kernel<<<dim3(HIDD / 128, T_TOK / 128), 256, gemm_smem>>>(pA, pB, out, HIDD);
    }
}

// round 17
// speedup vs baseline: 1.1458x; 1.0191x over previous
#include <cuda_runtime.h>
#include <cuda_bf16.h>
#include <cstdint>
#include <cstddef>

#define T_TOK   8192
#define HIDD    2048
#define NQKV    2560
#define DHEAD   256
#define NHEADS  8
#define SEQ     2048
#define NSLOTS  16384
#define KP2     4096        // 2-plane row: [hi 2048 | lo 2048]

// ---------------- scratch ----------------
__device__ float g_qkv[(size_t)T_TOK * NQKV];
__device__ __nv_bfloat16 g_packA[(size_t)T_TOK * KP2];
__device__ __nv_bfloat16 g_packB[(size_t)NQKV * KP2];
__device__ __nv_bfloat16 g_packW[(size_t)HIDD * KP2];   // wo pack (separate: prep once)
__device__ __nv_bfloat16 g_qpack[(size_t)T_TOK * NHEADS * 2 * DHEAD];
__device__ __nv_bfloat16 g_kpack[(size_t)T_TOK * 2 * DHEAD];
__device__ __nv_bfloat16 g_vpackT[(size_t)2 * DHEAD * T_TOK];
__device__ int g_tileCtr;

__device__ __forceinline__ uint32_t smem_u32(const void* p) {
    uint32_t a;
    asm("{ .reg .u64 t; cvta.to.shared.u64 t, %1; cvt.u32.u64 %0, t; }" : "=r"(a) : "l"(p));
    return a;
}

#define SWZ(o)   ((o) ^ (((o) >> 3) & 0x70))   // 128B rows
#define SWZ64(o) ((o) ^ (((o) >> 3) & 0x30))   // 64B rows

#define CP_ASYNC16(dst, src) \
    asm volatile("cp.async.cg.shared.global [%0], [%1], 16;" :: "r"(dst), "l"(src))
#define CP_COMMIT() asm volatile("cp.async.commit_group;" ::: "memory")
#define CP_WAIT(n)  asm volatile("cp.async.wait_group %0;" :: "n"(n) : "memory")

__device__ __forceinline__ void ldsm_x4(uint32_t* r, uint32_t addr) {
    asm volatile("ldmatrix.sync.aligned.m8n8.x4.shared.b16 {%0,%1,%2,%3}, [%4];"
        : "=r"(r[0]), "=r"(r[1]), "=r"(r[2]), "=r"(r[3]) : "r"(addr));
}

__device__ __forceinline__ void mma16816(float* d, const uint32_t* a, const uint32_t* b) {
    asm volatile(
        "mma.sync.aligned.m16n8k16.row.col.f32.bf16.bf16.f32 "
        "{%0,%1,%2,%3}, {%4,%5,%6,%7}, {%8,%9}, {%0,%1,%2,%3};"
        : "+f"(d[0]), "+f"(d[1]), "+f"(d[2]), "+f"(d[3])
        : "r"(a[0]), "r"(a[1]), "r"(a[2]), "r"(a[3]), "r"(b[0]), "r"(b[1]));
}

__device__ __forceinline__ uint32_t bf16pair(float a, float b) {
    __nv_bfloat16 ha = __float2bfloat16_rn(a), hb = __float2bfloat16_rn(b);
    uint16_t ua = *(uint16_t*)&ha, ub = *(uint16_t*)&hb;
    return (uint32_t)ua | ((uint32_t)ub << 16);
}

__device__ __forceinline__ void pack4(const float4 x, __nv_bfloat16* dst, long r, int k) {
    uint32_t hi0 = bf16pair(x.x, x.y);
    uint32_t hi1 = bf16pair(x.z, x.w);
    __nv_bfloat162 h0 = *(__nv_bfloat162*)&hi0;
    __nv_bfloat162 h1 = *(__nv_bfloat162*)&hi1;
    uint32_t lo0 = bf16pair(x.x - __bfloat162float(h0.x), x.y - __bfloat162float(h0.y));
    uint32_t lo1 = bf16pair(x.z - __bfloat162float(h1.x), x.w - __bfloat162float(h1.y));
    *(uint2*)(dst + r * KP2 + k)        = make_uint2(hi0, hi1);
    *(uint2*)(dst + r * KP2 + 2048 + k) = make_uint2(lo0, lo1);
}

// ---------------------------------------------------------------------------
// Fused prep: pack hidden->packA, wqkv->packB, wo->packW, copy both caches.
// One launch; flat grid, 4 fp32 elems per thread per job.
// Job layout (in float4 units):
//   [0, J1)         hidden pack   J1 = T_TOK*HIDD/4      = 4194304
//   [J1, J2)        wqkv pack     J2 = J1 + NQKV*HIDD/4  = +1310720
//   [J2, J3)        wo pack       J3 = J2 + HIDD*HIDD/4  = +1048576
//   [J3, J4)        cache copy    J4 = J3 + NSLOTS*DHEAD/4 = +1048576 (k+v both)
// ---------------------------------------------------------------------------
#define PREP_J1 4194304L
#define PREP_J2 (PREP_J1 + 1310720L)
#define PREP_J3 (PREP_J2 + 1048576L)
#define PREP_J4 (PREP_J3 + 1048576L)

__global__ void prep_kernel(const float4* __restrict__ hidden,
                            const float4* __restrict__ wqkv,
                            const float4* __restrict__ wo,
                            const float4* __restrict__ kc_in,
                            const float4* __restrict__ vc_in,
                            float4* __restrict__ kc_out,
                            float4* __restrict__ vc_out,
                            __nv_bfloat16* __restrict__ pA,
                            __nv_bfloat16* __restrict__ pB,
                            __nv_bfloat16* __restrict__ pW)
{
    long idx = (long)blockIdx.x * blockDim.x + threadIdx.x;
    if (idx < PREP_J1) {
        long e = idx * 4;
        pack4(hidden[idx], pA, e >> 11, (int)(e & 2047));
    } else if (idx < PREP_J2) {
        long i = idx - PREP_J1;
        long e = i * 4;
        pack4(wqkv[i], pB, e >> 11, (int)(e & 2047));
    } else if (idx < PREP_J3) {
        long i = idx - PREP_J2;
        long e = i * 4;
        pack4(wo[i], pW, e >> 11, (int)(e & 2047));
    } else if (idx < PREP_J4) {
        long i = idx - PREP_J3;
        kc_out[i] = kc_in[i];
        vc_out[i] = vc_in[i];
    }
}

// ---------------------------------------------------------------------------
// 2-plane bf16x3 NT GEMM, occupancy-2, NON-persistent (verified form).
// ---------------------------------------------------------------------------
#define PLANE3   8192
#define STAGE3   32768
#define NCH3     64

__global__ __launch_bounds__(256, 2)
void gemm_mma3_kernel(const __nv_bfloat16* __restrict__ A,
                      const __nv_bfloat16* __restrict__ B,
                      float* __restrict__ C, int ldc)
{
    extern __shared__ char smc[];
    const uint32_t sbase = smem_u32(smc);
    const int tid  = threadIdx.x;
    const int warp = tid >> 5, lane = tid & 31;
    const int wm = (warp & 3) * 32;
    const int wn = (warp >> 2) * 64;
    const int mBase = blockIdx.y * 128;
    const int nBase = blockIdx.x * 128;

    const int lrow = tid >> 1;
    const int lu0  = (tid & 1) * 2;

    const char* Ag = (const char*)A + (size_t)(mBase + lrow) * (KP2 * 2) + lu0 * 16;
    const char* Bg = (const char*)B + (size_t)(nBase + lrow) * (KP2 * 2) + lu0 * 16;

#define LOAD_STAGE3(stage, chunk) do {                                        \
    uint32_t _s = sbase + (stage) * STAGE3;                                   \
    size_t _go = (size_t)(chunk) * 64;                                        \
    _Pragma("unroll")                                                         \
    for (int _u = 0; _u < 2; _u++) {                                          \
        uint32_t _sw = SWZ64((uint32_t)(lrow * 64 + (lu0 + _u) * 16));        \
        CP_ASYNC16(_s + _sw,              Ag + _go + _u * 16);                \
        CP_ASYNC16(_s + PLANE3 + _sw,     Ag + 4096 + _go + _u * 16);         \
        CP_ASYNC16(_s + 2 * PLANE3 + _sw, Bg + _go + _u * 16);                \
        CP_ASYNC16(_s + 3 * PLANE3 + _sw, Bg + 4096 + _go + _u * 16);         \
    } } while (0)

    float acc[2][8][4];
    #pragma unroll
    for (int i = 0; i < 2; i++)
        #pragma unroll
        for (int j = 0; j < 8; j++)
            #pragma unroll
            for (int q = 0; q < 4; q++) acc[i][j][q] = 0.f;

    LOAD_STAGE3(0, 0); CP_COMMIT();
    LOAD_STAGE3(1, 1); CP_COMMIT();

    const uint32_t arow = wm + (lane & 15);
    const uint32_t acol16 = (lane >> 4) * 16;
    const uint32_t brow_lo = wn + (lane & 7) + ((lane >> 4) * 8);
    const uint32_t bcol16 = ((lane >> 3) & 1) * 16;

    int stage = 0;
    for (int it = 0; it < NCH3; it++) {
        CP_WAIT(1);
        __syncthreads();
        const uint32_t s0 = sbase + stage * STAGE3;

        #pragma unroll
        for (int ks = 0; ks < 2; ks++) {
            uint32_t aH0[4], aH1[4], aL0[4], aL1[4];
            uint32_t ao = arow * 64 + ks * 32 + acol16;
            uint32_t swa0 = SWZ64(ao), swa1 = SWZ64(ao + 16 * 64);
            ldsm_x4(aH0, s0 + swa0);
            ldsm_x4(aH1, s0 + swa1);
            ldsm_x4(aL0, s0 + PLANE3 + swa0);
            ldsm_x4(aL1, s0 + PLANE3 + swa1);
            #pragma unroll
            for (int nt = 0; nt < 4; nt++) {
                uint32_t bo = (brow_lo + nt * 16) * 64 + ks * 32 + bcol16;
                uint32_t swb = SWZ64(bo);
                uint32_t bH[4], bL[4];
                ldsm_x4(bH, s0 + 2 * PLANE3 + swb);
                ldsm_x4(bL, s0 + 3 * PLANE3 + swb);
                mma16816(acc[0][nt * 2],     aH0, &bH[0]);
                mma16816(acc[0][nt * 2 + 1], aH0, &bH[2]);
                mma16816(acc[1][nt * 2],     aH1, &bH[0]);
                mma16816(acc[1][nt * 2 + 1], aH1, &bH[2]);
                mma16816(acc[0][nt * 2],     aL0, &bH[0]);
                mma16816(acc[0][nt * 2 + 1], aL0, &bH[2]);
                mma16816(acc[1][nt * 2],     aL1, &bH[0]);
                mma16816(acc[1][nt * 2 + 1], aL1, &bH[2]);
                mma16816(acc[0][nt * 2],     aH0, &bL[0]);
                mma16816(acc[0][nt * 2 + 1], aH0, &bL[2]);
                mma16816(acc[1][nt * 2],     aH1, &bL[0]);
                mma16816(acc[1][nt * 2 + 1], aH1, &bL[2]);
            }
        }

        int nx = it + 2;
        if (nx < NCH3) {
            int ns = stage + 2; if (ns >= 3) ns -= 3;
            LOAD_STAGE3(ns, nx);
        }
        CP_COMMIT();
        if (++stage == 3) stage = 0;
    }
#undef LOAD_STAGE3

    const int r0 = mBase + wm + (lane >> 2);
    const int c0 = nBase + wn + (lane & 3) * 2;
    #pragma unroll
    for (int mt = 0; mt < 2; mt++) {
        #pragma unroll
        for (int nt = 0; nt < 8; nt++) {
            const int r = r0 + mt * 16;
            const int c = c0 + nt * 8;
            *(float2*)&C[(size_t)r * ldc + c]       = make_float2(acc[mt][nt][0], acc[mt][nt][1]);
            *(float2*)&C[(size_t)(r + 8) * ldc + c] = make_float2(acc[mt][nt][2], acc[mt][nt][3]);
        }
    }
}

// ---------------------------------------------------------------------------
// Fused RoPE + Q/K pack + cache scatter + V transpose/split (V cache write
// moved into transpose phase — single V read). Resets tile dispenser.
// ---------------------------------------------------------------------------
#define QSCL 0.09016844335f   // D^-1/2 * log2(e)

__global__ __launch_bounds__(512)
void ropevt_kernel(const float* __restrict__ qkv,
                   const float* __restrict__ cosp,
                   const float* __restrict__ sinp,
                   const int* __restrict__ slots,
                   float* __restrict__ kc_out,
                   float* __restrict__ vc_out,
                   __nv_bfloat16* __restrict__ qpack,
                   __nv_bfloat16* __restrict__ kpack,
                   __nv_bfloat16* __restrict__ vt)
{
    __shared__ float tile[64][33];
    const int tid = threadIdx.x;
    const int t0 = blockIdx.x * 64;

    if (blockIdx.x == 0 && tid == 0) g_tileCtr = 0;

    // ---- phase 1: rope + Q/K packs + K cache scatter
    #pragma unroll 4
    for (int i = 0; i < 16; i++) {
        int idx = i * 512 + tid;
        int d = idx & 127, tl = idx >> 7;
        int t = t0 + tl;
        const float c = cosp[t * 128 + d];
        const float s = sinp[t * 128 + d];
        const float* row = qkv + (size_t)t * NQKV;

        #pragma unroll
        for (int h = 0; h < NHEADS; h++) {
            float x1 = row[h * DHEAD + d], x2 = row[h * DHEAD + d + 128];
            float y1 = (x1 * c - x2 * s) * QSCL;
            float y2 = (x2 * c + x1 * s) * QSCL;
            __nv_bfloat16 h1 = __float2bfloat16_rn(y1);
            __nv_bfloat16 h2 = __float2bfloat16_rn(y2);
            __nv_bfloat16* qp = qpack + ((size_t)(t * NHEADS + h) * 2) * DHEAD;
            qp[d] = h1; qp[d + 128] = h2;
            qp[DHEAD + d]       = __float2bfloat16_rn(y1 - __bfloat162float(h1));
            qp[DHEAD + d + 128] = __float2bfloat16_rn(y2 - __bfloat162float(h2));
        }
        {
            float x1 = row[NHEADS * DHEAD + d], x2 = row[NHEADS * DHEAD + d + 128];
            float y1 = x1 * c - x2 * s;
            float y2 = x2 * c + x1 * s;
            const int slot = slots[t];
            kc_out[(size_t)slot * DHEAD + d]       = y1;
            kc_out[(size_t)slot * DHEAD + 128 + d] = y2;
            __nv_bfloat16 h1 = __float2bfloat16_rn(y1);
            __nv_bfloat16 h2 = __float2bfloat16_rn(y2);
            __nv_bfloat16* kp = kpack + (size_t)t * 2 * DHEAD;
            kp[d] = h1; kp[d + 128] = h2;
            kp[DHEAD + d]       = __float2bfloat16_rn(y1 - __bfloat162float(h1));
            kp[DHEAD + d + 128] = __float2bfloat16_rn(y2 - __bfloat162float(h2));
        }
    }

    // ---- phase 2: V transpose + hi/lo split + V cache scatter (single read)
    for (int d0 = 0; d0 < DHEAD; d0 += 32) {
        __syncthreads();
        #pragma unroll
        for (int w = 0; w < 4; w++) {
            int lin = w * 512 + tid;
            int dl = lin & 31, tl = lin >> 5;
            float v = qkv[(size_t)(t0 + tl) * NQKV + (NHEADS + 1) * DHEAD + d0 + dl];
            tile[tl][dl] = v;
            const int slot = slots[t0 + tl];
            vc_out[(size_t)slot * DHEAD + d0 + dl] = v;
        }
        __syncthreads();
        #pragma unroll
        for (int w = 0; w < 4; w++) {
            int lin = w * 512 + tid;
            int dl = lin >> 6, tl = lin & 63;
            float x = tile[tl][dl];
            __nv_bfloat16 hi = __float2bfloat16_rn(x);
            __nv_bfloat16 lo = __float2bfloat16_rn(x - __bfloat162float(hi));
            size_t base = (size_t)(d0 + dl) * T_TOK + t0 + tl;
            vt[base] = hi;
            vt[(size_t)DHEAD * T_TOK + base] = lo;
        }
    }
}

// ---------------------------------------------------------------------------
// Tensor-core flash attention: bf16x3, Q hoisted, persistent + dynamic LPT
// dispenser, max-free softmax, K double-buffered. (verified R16 form)
// ---------------------------------------------------------------------------
#define KA_HI  0u
#define KB_HI  65536u
#define V_HI   131072u
#define V_LO   163840u
#define P_HI   196608u
#define P_LO   204800u
#define RED_S  212992u
#define TIDX   213504u
#define ATTN_SMEM 213632
#define N_ATTN_TILES ((SEQ / 64) * NHEADS * 4)

__global__ __launch_bounds__(256, 1)
void attn_mma_kernel(const __nv_bfloat16* __restrict__ qpack,
                     const __nv_bfloat16* __restrict__ kpack,
                     const __nv_bfloat16* __restrict__ vpackT,
                     __nv_bfloat16* __restrict__ opack)
{
    extern __shared__ char smem[];
    const uint32_t sb = smem_u32(smem);
    float* smf = (float*)smem;
    int* tix = (int*)(smem + TIDX);

    const int tid  = threadIdx.x;
    const int warp = tid >> 5, lane = tid & 31;
    const int wm = warp & 3, wn = warp >> 2;

    const uint32_t arow   = (uint32_t)(wm * 16 + (lane & 15));
    const uint32_t acol16 = (uint32_t)((lane >> 4) * 16);
    const uint32_t brlo   = (uint32_t)((lane & 7) + ((lane >> 4) << 3));
    const uint32_t bcol16 = (uint32_t)(((lane >> 3) & 1) * 16);
    const int rbase = wm * 16 + (lane >> 2);

    while (true) {
        if (tid == 0) *tix = atomicAdd(&g_tileCtr, 1);
        __syncthreads();
        const int idx = *tix;
        if (idx >= N_ATTN_TILES) break;

        const int qb = (SEQ / 64 - 1) - (idx >> 5);
        const int h  = (idx & 31) >> 2;
        const int b  = idx & 3;
        const int t0 = b * SEQ + qb * 64;

        // prologue: Q -> KB (staging), K0 -> KA
        #pragma unroll
        for (int p = 0; p < 2; p++) {
            #pragma unroll
            for (int i = 0; i < 8; i++) {
                int li = i * 256 + tid;
                int tl = li >> 5, c16 = li & 31;
                const char* src = (const char*)(qpack +
                    (((size_t)(t0 + tl) * NHEADS + h) * 2 + p) * DHEAD + c16 * 8);
                uint32_t dst = sb + KB_HI + p * 32768u +
                               (uint32_t)(c16 >> 3) * 8192u +
                               SWZ((uint32_t)(tl * 128 + (c16 & 7) * 16));
                CP_ASYNC16(dst, src);
            }
        }
        {
            int tk0 = b * SEQ;
            #pragma unroll
            for (int p = 0; p < 2; p++) {
                #pragma unroll
                for (int i = 0; i < 8; i++) {
                    int li = i * 256 + tid;
                    int tl = li >> 5, c16 = li & 31;
                    const char* src = (const char*)(kpack +
                        ((size_t)(tk0 + tl) * 2 + p) * DHEAD + c16 * 8);
                    uint32_t dst = sb + KA_HI + p * 32768u +
                                   (uint32_t)(c16 >> 3) * 8192u +
                                   SWZ((uint32_t)(tl * 128 + (c16 & 7) * 16));
                    CP_ASYNC16(dst, src);
                }
            }
        }
        CP_COMMIT();

        float O[16][4];
        #pragma unroll
        for (int i = 0; i < 16; i++)
            #pragma unroll
            for (int j = 0; j < 4; j++) O[i][j] = 0.f;
        float sumAcc0 = 0.f, sumAcc1 = 0.f;

        CP_WAIT(0);
        __syncthreads();
        uint32_t qf[2][16][4];
        #pragma unroll
        for (int p = 0; p < 2; p++)
            #pragma unroll
            for (int ks = 0; ks < 16; ks++) {
                uint32_t off = (uint32_t)(ks >> 2) * 8192u +
                               SWZ(arow * 128 + (ks & 3) * 32 + acol16);
                ldsm_x4(qf[p][ks], sb + KB_HI + p * 32768u + off);
            }

        for (int kt = 0; kt <= qb; kt++) {
            CP_WAIT(0);
            __syncthreads();

            const int tkv = b * SEQ + kt * 64;
            #pragma unroll
            for (int p = 0; p < 2; p++) {
                #pragma unroll
                for (int i = 0; i < 8; i++) {
                    int li = i * 256 + tid;
                    int dl = li >> 3, c16 = li & 7;
                    const char* src = (const char*)(vpackT +
                        (size_t)p * DHEAD * T_TOK + (size_t)dl * T_TOK + tkv + c16 * 8);
                    uint32_t dst = sb + V_HI + p * 32768u +
                                   SWZ((uint32_t)(dl * 128 + c16 * 16));
                    CP_ASYNC16(dst, src);
                }
            }
            CP_COMMIT();
            if (kt < qb) {
                const int tk1 = b * SEQ + (kt + 1) * 64;
                const uint32_t kb1 = ((kt + 1) & 1) ? KB_HI : KA_HI;
                #pragma unroll
                for (int p = 0; p < 2; p++) {
                    #pragma unroll
                    for (int i = 0; i < 8; i++) {
                        int li = i * 256 + tid;
                        int tl = li >> 5, c16 = li & 31;
                        const char* src = (const char*)(kpack +
                            ((size_t)(tk1 + tl) * 2 + p) * DHEAD + c16 * 8);
                        uint32_t dst = sb + kb1 + p * 32768u +
                                       (uint32_t)(c16 >> 3) * 8192u +
                                       SWZ((uint32_t)(tl * 128 + (c16 & 7) * 16));
                        CP_ASYNC16(dst, src);
                    }
                }
                CP_COMMIT();
            }

            const uint32_t kb0 = (kt & 1) ? KB_HI : KA_HI;
            float s[4][4];
            #pragma unroll
            for (int i = 0; i < 4; i++)
                #pragma unroll
                for (int j = 0; j < 4; j++) s[i][j] = 0.f;

            #pragma unroll
            for (int ks = 0; ks < 16; ks++) {
                const uint32_t blk = (uint32_t)(ks >> 2) * 8192u;
                #pragma unroll
                for (int nt = 0; nt < 2; nt++) {
                    uint32_t brow = (uint32_t)(wn * 32 + nt * 16) + brlo;
                    uint32_t swb = blk + SWZ(brow * 128 + (ks & 3) * 32 + bcol16);
                    uint32_t bH[4], bL[4];
                    ldsm_x4(bH, sb + kb0 + swb);
                    ldsm_x4(bL, sb + kb0 + 32768u + swb);
                    mma16816(s[nt * 2],     qf[0][ks], &bH[0]);
                    mma16816(s[nt * 2 + 1], qf[0][ks], &bH[2]);
                    mma16816(s[nt * 2],     qf[1][ks], &bH[0]);
                    mma16816(s[nt * 2 + 1], qf[1][ks], &bH[2]);
                    mma16816(s[nt * 2],     qf[0][ks], &bL[0]);
                    mma16816(s[nt * 2 + 1], qf[0][ks], &bL[2]);
                }
            }

            if (kt == qb) {
                #pragma unroll
                for (int nf = 0; nf < 4; nf++) {
                    int c = wn * 32 + nf * 8 + (lane & 3) * 2;
                    #pragma unroll
                    for (int half = 0; half < 2; half++) {
                        int r = rbase + half * 8;
                        if (c     > r) s[nf][half * 2]     = -1e30f;
                        if (c + 1 > r) s[nf][half * 2 + 1] = -1e30f;
                    }
                }
            }

            #pragma unroll
            for (int half = 0; half < 2; half++) {
                int r = rbase + half * 8;
                #pragma unroll
                for (int nf = 0; nf < 4; nf++) {
                    int c = wn * 32 + nf * 8 + (lane & 3) * 2;
                    float p0 = exp2f(s[nf][half * 2]);
                    float p1 = exp2f(s[nf][half * 2 + 1]);
                    if (half == 0) sumAcc0 += p0 + p1; else sumAcc1 += p0 + p1;
                    __nv_bfloat16 h0 = __float2bfloat16_rn(p0);
                    __nv_bfloat16 h1 = __float2bfloat16_rn(p1);
                    float l0 = p0 - __bfloat162float(h0);
                    float l1 = p1 - __bfloat162float(h1);
                    uint32_t off = SWZ((uint32_t)(r * 128 + c * 2));
                    uint16_t u0 = *(uint16_t*)&h0, u1 = *(uint16_t*)&h1;
                    *(uint32_t*)(smem + P_HI + off) = (uint32_t)u0 | ((uint32_t)u1 << 16);
                    *(uint32_t*)(smem + P_LO + off) = bf16pair(l0, l1);
                }
            }

            if (kt < qb) { CP_WAIT(1); }
            else         { CP_WAIT(0); }
            __syncthreads();

            #pragma unroll
            for (int ks = 0; ks < 4; ks++) {
                uint32_t aH[4], aL[4];
                uint32_t ao = SWZ(arow * 128 + ks * 32 + acol16);
                ldsm_x4(aH, sb + P_HI + ao);
                ldsm_x4(aL, sb + P_LO + ao);
                #pragma unroll
                for (int nt = 0; nt < 8; nt++) {
                    uint32_t brow = (uint32_t)(wn * 128 + nt * 16) + brlo;
                    uint32_t bo = SWZ(brow * 128 + ks * 32 + bcol16);
                    uint32_t bH[4], bL[4];
                    ldsm_x4(bH, sb + V_HI + bo);
                    ldsm_x4(bL, sb + V_LO + bo);
                    mma16816(O[nt * 2],     aH, &bH[0]);
                    mma16816(O[nt * 2 + 1], aH, &bH[2]);
                    mma16816(O[nt * 2],     aL, &bH[0]);
                    mma16816(O[nt * 2 + 1], aL, &bH[2]);
                    mma16816(O[nt * 2],     aH, &bL[0]);
                    mma16816(O[nt * 2 + 1], aH, &bL[2]);
                }
            }
        }

        sumAcc0 += __shfl_xor_sync(0xffffffffu, sumAcc0, 1);
        sumAcc0 += __shfl_xor_sync(0xffffffffu, sumAcc0, 2);
        sumAcc1 += __shfl_xor_sync(0xffffffffu, sumAcc1, 1);
        sumAcc1 += __shfl_xor_sync(0xffffffffu, sumAcc1, 2);
        if ((lane & 3) == 0) {
            smf[RED_S / 4 + wn * 64 + rbase]     = sumAcc0;
            smf[RED_S / 4 + wn * 64 + rbase + 8] = sumAcc1;
        }
        __syncthreads();
        float inv0 = 1.0f / (smf[RED_S / 4 + rbase]     + smf[RED_S / 4 + 64 + rbase]);
        float inv1 = 1.0f / (smf[RED_S / 4 + rbase + 8] + smf[RED_S / 4 + 64 + rbase + 8]);

        #pragma unroll
        for (int half = 0; half < 2; half++) {
            const int r = rbase + half * 8;
            const float inv = half ? inv1 : inv0;
            __nv_bfloat16* orow = opack + (size_t)(t0 + r) * KP2 + h * DHEAD;
            #pragma unroll
            for (int nt = 0; nt < 16; nt++) {
                int c = wn * 128 + nt * 8 + (lane & 3) * 2;
                float o0 = O[nt][half * 2]     * inv;
                float o1 = O[nt][half * 2 + 1] * inv;
                __nv_bfloat16 h0 = __float2bfloat16_rn(o0);
                __nv_bfloat16 h1 = __float2bfloat16_rn(o1);
                uint32_t hi = (uint32_t)(*(uint16_t*)&h0) | ((uint32_t)(*(uint16_t*)&h1) << 16);
                uint32_t lo = bf16pair(o0 - __bfloat162float(h0), o1 - __bfloat162float(h1));
                *(uint32_t*)(orow + c)        = hi;
                *(uint32_t*)(orow + 2048 + c) = lo;
            }
        }
        __syncthreads();
    }
}

// ---------------------------------------------------------------------------
// Launch: 5 kernels total.
// ---------------------------------------------------------------------------
extern "C" void kernel_launch(void* const* d_in, const int* in_sizes, int n_in,
                              void* d_out, int out_size)
{
    (void)in_sizes; (void)n_in; (void)out_size;
    const float* hidden = (const float*)d_in[0];
    const float* cosp   = (const float*)d_in[1];
    const float* sinp   = (const float*)d_in[2];
    const int*   slots  = (const int*)d_in[3];
    const float* kc_in  = (const float*)d_in[4];
    const float* vc_in  = (const float*)d_in[5];
    const float* wqkv   = (const float*)d_in[6];
    const float* wo     = (const float*)d_in[7];

    float* out    = (float*)d_out;
    float* kc_out = out + (size_t)T_TOK * HIDD;
    float* vc_out = kc_out + (size_t)NSLOTS * DHEAD;

    float* qkv = nullptr;
    __nv_bfloat16 *pA = nullptr, *pB = nullptr, *pW = nullptr,
                  *qp = nullptr, *kp = nullptr, *vt = nullptr;
    cudaGetSymbolAddress((void**)&qkv, g_qkv);
    cudaGetSymbolAddress((void**)&pA,  g_packA);
    cudaGetSymbolAddress((void**)&pB,  g_packB);
    cudaGetSymbolAddress((void**)&pW,  g_packW);
    cudaGetSymbolAddress((void**)&qp,  g_qpack);
    cudaGetSymbolAddress((void**)&kp,  g_kpack);
    cudaGetSymbolAddress((void**)&vt,  g_vpackT);

    const int gemm_smem = 3 * STAGE3;   // 98304 -> 2 CTAs/SM
    cudaFuncSetAttribute(gemm_mma3_kernel,
                         cudaFuncAttributeMaxDynamicSharedMemorySize, gemm_smem);
    cudaFuncSetAttribute(attn_mma_kernel,
                         cudaFuncAttributeMaxDynamicSharedMemorySize, ATTN_SMEM);

    // #1: fused prep (all packs + cache passthrough)
    prep_kernel<<<(unsigned)((PREP_J4 + 255) / 256), 256>>>(
        (const float4*)hidden, (const float4*)wqkv, (const float4*)wo,
        (const float4*)kc_in, (const float4*)vc_in,
        (float4*)kc_out, (float4*)vc_out, pA, pB, pW);

    // #2: QKV projection
    gemm_mma3_kernel<<<dim3(NQKV / 128, T_TOK / 128), 256, gemm_smem>>>(pA, pB, qkv, NQKV);

    // #3: fused RoPE + packs + cache scatter + V transpose (+ ctr reset)
    ropevt_kernel<<<T_TOK / 64, 512>>>(qkv, cosp, sinp, slots, kc_out, vc_out, qp, kp, vt);

    // #4: persistent dynamic-scheduled tensor-core flash attention
    attn_mma_kernel<<<148, 256, ATTN_SMEM>>>(qp, kp, vt, pA);

    // #5: output projection
    gemm_mma3_kernel<<<dim3(HIDD / 128, T_TOK / 128), 256, gemm_smem>>>(pA, pW, out, HIDD);
}